// round 9
// baseline (speedup 1.0000x reference)
#include <cuda_runtime.h>
#include <math.h>

typedef unsigned long long ull;

#define NB   512
#define DM   128
#define DOUT 64
#define DP   32
#define NPIX 225
#define PSTR 228          // global per-channel pixel stride (floats)
#define PADP 292          // padded 17x17 (289) channel stride in smem
#define XST  256          // smem dense pixel stride
#define MAXF 31.75f
#define INV_MAXF (1.0f/31.75f)
#define MAXM (127.0f/3.515625f)

#define SMA ((DM*PADP + DM*DM)*4)     // k_layer smem: padded acts + weight tile
#define SMB ((DM*XST  + DM*DM)*4)     // k_res smem: dense acts + weight tile
#define SMC (DM*XST*4 + DOUT*PADP*4)  // k_fin smem

// ---------------- device scratch (no allocation) ----------------
__device__ __align__(16) float g_xs [4ull*NB*DM*PSTR];
__device__ __align__(16) float g_wdc[12*DM*DM];   // dconv  [l*3+t][i][o]
__device__ __align__(16) float g_wc1[4*DM*DM];    // c1     [l][i][o]
__device__ __align__(16) float g_wr1[DM*DM];      // r0_w1  [i][o]
__device__ __align__(16) float g_wr2[DM*DM];      // r0_w2  [i][o]
__device__ __align__(16) float g_wfn[DM*DOUT];    // fin    [i][o]

// tap offsets (dr,dc): tap t reads x[h+dr][w+dc]
__constant__ int c_dr[4][3] = {{0,0,0},{-1,0,1},{-1,0,1},{1,0,-1}};
__constant__ int c_dc[4][3] = {{-1,0,1},{0,0,0},{-1,0,1},{-1,0,1}};

// ---------------- f32x2 helpers ----------------
__device__ __forceinline__ ull pack2(float lo, float hi) {
    ull r; asm("mov.b64 %0, {%1,%2};" : "=l"(r) : "f"(lo), "f"(hi)); return r;
}
__device__ __forceinline__ float2 unpack2(ull v) {
    float2 f; asm("mov.b64 {%0,%1}, %2;" : "=f"(f.x), "=f"(f.y) : "l"(v)); return f;
}
__device__ __forceinline__ ull fma2(ull a, ull b, ull c) {
    ull d; asm("fma.rn.f32x2 %0, %1, %2, %3;" : "=l"(d) : "l"(a), "l"(b), "l"(c)); return d;
}
__device__ __forceinline__ float silu(float x) {
    return __fdividef(x, 1.f + __expf(-x));
}

// ---------------- transpose: dconv [12][o][i] -> [12][i][o] ----------------
__global__ void k_xpose(const float* __restrict__ src, float* __restrict__ dst,
                        int nmat, int R, int C) {
    int n = nmat * R * C;
    for (int idx = blockIdx.x * blockDim.x + threadIdx.x; idx < n;
         idx += gridDim.x * blockDim.x) {
        int m = idx / (R * C);
        int rem = idx - m * R * C;
        int r = rem / C, c = rem - r * C;
        dst[(m * C + c) * R + r] = src[idx];
    }
}

// ---------------- transpose the remaining 4 weight families in ONE launch ----------------
__global__ void k_xpose_rest(const float* __restrict__ c1,
                             const float* __restrict__ r1,
                             const float* __restrict__ r2,
                             const float* __restrict__ fin,
                             float* __restrict__ wc1, float* __restrict__ wr1,
                             float* __restrict__ wr2, float* __restrict__ wfn) {
    const int N1 = 4 * DM * DM;
    const int N2 = N1 + DM * DM;
    const int N3 = N2 + DM * DM;
    const int N4 = N3 + DOUT * DM;
    for (int idx = blockIdx.x * blockDim.x + threadIdx.x; idx < N4;
         idx += gridDim.x * blockDim.x) {
        if (idx < N1) {
            int m = idx / (DM * DM);
            int rem = idx - m * DM * DM;
            int r = rem / DM, c = rem - r * DM;
            wc1[(m * DM + c) * DM + r] = c1[idx];
        } else if (idx < N2) {
            int i2 = idx - N1;
            int r = i2 / DM, c = i2 - r * DM;
            wr1[c * DM + r] = r1[i2];
        } else if (idx < N3) {
            int i2 = idx - N2;
            int r = i2 / DM, c = i2 - r * DM;
            wr2[c * DM + r] = r2[i2];
        } else {
            int i2 = idx - N3;
            int r = i2 / DM, c = i2 - r * DM;  // r = o (64), c = i (128)
            wfn[c * DOUT + r] = fin[i2];
        }
    }
}

// ---------------- input map conv (2 -> 128) + silu ----------------
__global__ __launch_bounds__(256) void k_map(const float* __restrict__ x,
                                             const float* __restrict__ mw,
                                             const float* __restrict__ mb,
                                             float* __restrict__ xsb) {
    int b = blockIdx.x, d = blockIdx.y, tid = threadIdx.x;
    __shared__ float xp[2 * PADP];
    for (int i = tid; i < 2 * PADP; i += 256) xp[i] = 0.f;
    __syncthreads();
    const float* xb = x + (size_t)b * 2 * NPIX;
    for (int i = tid; i < 2 * NPIX; i += 256) {
        int c = i / NPIX, p = i - c * NPIX;
        int h = p / 15, w = p - h * 15;
        xp[c * PADP + (h + 1) * 17 + (w + 1)] = xb[i];
    }
    __syncthreads();
    int dr[3], dc[3];
#pragma unroll
    for (int t = 0; t < 3; t++) { dr[t] = c_dr[d][t]; dc[t] = c_dc[d][t]; }
    float* dst = xsb + (size_t)(d * NB + b) * DM * PSTR;
    for (int idx = tid; idx < DM * NPIX; idx += 256) {
        int o = idx / NPIX, p = idx - o * NPIX;
        int h = p / 15, w = p - h * 15;
        float acc = mb[o];
#pragma unroll
        for (int t = 0; t < 3; t++) {
            int off = (h + 1 + dr[t]) * 17 + (w + 1 + dc[t]);
            acc += mw[(t * DM + o) * 2 + 0] * xp[off]
                 + mw[(t * DM + o) * 2 + 1] * xp[PADP + off];
        }
        dst[o * PSTR + p] = silu(acc);
    }
}

// -------- fused layer: xs = xs + silu(c1 @ silu(dirconv(xs))) --------
// Phase A: dirconv 3-tap 128->128 into registers (16 warps x 16 o x 128 px).
// Phase B: silu -> dense smem tile -> pointwise c1 -> silu -> +residual -> xs.
__global__ __launch_bounds__(512, 1) void k_layer(float* __restrict__ xsb,
                                                  const float* __restrict__ wTdc, // [3][i][o]
                                                  const float* __restrict__ bdc,
                                                  const float* __restrict__ wTc1, // [i][o]
                                                  const float* __restrict__ bc1) {
    extern __shared__ float smbuf[];
    float* xpad = smbuf;              // DM*PADP (phase A); dense DM*XST (phase B)
    float* wsm  = smbuf + DM * PADP;  // DM*DM weight tile
    int b = blockIdx.x, d = blockIdx.y;
    int tid = threadIdx.x, lane = tid & 31, wid = tid >> 5;
    float* xsg = xsb + (size_t)(d * NB + b) * DM * PSTR;

    for (int i = tid; i < DM * PADP; i += 512) xpad[i] = 0.f;
    __syncthreads();
    for (int c = wid; c < DM; c += 16) {
        const float* s = xsg + c * PSTR;
        float* xq = xpad + c * PADP;
        for (int p = lane; p < NPIX; p += 32) {
            int h = p / 15, w = p - h * 15;
            xq[(h + 1) * 17 + (w + 1)] = s[p];
        }
    }

    const int pg    = wid >> 3;         // pixel group 0/1
    const int obase = (wid & 7) * 16;   // warp's 16 output channels
    const int pbase = pg * 128 + lane;

    int offs[3][4];
#pragma unroll
    for (int k = 0; k < 4; k++) {
        int p = pbase + 32 * k;
        int pv = (p < NPIX) ? p : 0;
        int h = pv / 15, w = pv - h * 15;
#pragma unroll
        for (int t = 0; t < 3; t++)
            offs[t][k] = (h + 1 + c_dr[d][t]) * 17 + (w + 1 + c_dc[d][t]);
    }

    ull acc[8][4];
#pragma unroll
    for (int j = 0; j < 8; j++)
#pragma unroll
        for (int k = 0; k < 4; k++) acc[j][k] = 0ull;

    for (int t = 0; t < 3; t++) {
        __syncthreads();   // wsm free of prior readers; xpad writes visible (t=0)
        {
            const float4* ws = (const float4*)(wTdc + t * DM * DM);
            float4* wd = (float4*)wsm;
#pragma unroll
            for (int j = 0; j < 8; j++) wd[tid + 512 * j] = ws[tid + 512 * j];
        }
        __syncthreads();

        for (int i = 0; i < DM; i++) {
            const float* xr = xpad + i * PADP;
            const float* wrow = wsm + i * DM + obase;
            ulonglong2 wa = *(const ulonglong2*)(wrow);
            ulonglong2 wb = *(const ulonglong2*)(wrow + 4);
            ulonglong2 wc = *(const ulonglong2*)(wrow + 8);
            ulonglong2 we = *(const ulonglong2*)(wrow + 12);
#pragma unroll
            for (int k = 0; k < 4; k++) {
                float xv = xr[offs[t][k]];
                ull xx = pack2(xv, xv);
                acc[0][k] = fma2(xx, wa.x, acc[0][k]);
                acc[1][k] = fma2(xx, wa.y, acc[1][k]);
                acc[2][k] = fma2(xx, wb.x, acc[2][k]);
                acc[3][k] = fma2(xx, wb.y, acc[3][k]);
                acc[4][k] = fma2(xx, wc.x, acc[4][k]);
                acc[5][k] = fma2(xx, wc.y, acc[5][k]);
                acc[6][k] = fma2(xx, we.x, acc[6][k]);
                acc[7][k] = fma2(xx, we.y, acc[7][k]);
            }
        }
    }

    __syncthreads();   // everyone done reading xpad + wsm
    // dense tile = silu(dirconv + bias); garbage at p>=225 is harmless (never stored)
    float* dense = smbuf;
#pragma unroll
    for (int j = 0; j < 8; j++) {
        int o0 = obase + 2 * j;
        float b0 = bdc[o0], b1 = bdc[o0 + 1];
        float* t0 = dense + o0 * XST;
        float* t1 = t0 + XST;
#pragma unroll
        for (int k = 0; k < 4; k++) {
            int p = pbase + 32 * k;
            if (p < NPIX) {
                float2 v = unpack2(acc[j][k]);
                t0[p] = silu(v.x + b0);
                t1[p] = silu(v.y + b1);
            }
        }
    }
    {   // stage c1 weights (distinct smem region; concurrent with dense writes)
        const float4* ws = (const float4*)wTc1;
        float4* wd = (float4*)wsm;
#pragma unroll
        for (int j = 0; j < 8; j++) wd[tid + 512 * j] = ws[tid + 512 * j];
    }
    __syncthreads();

    // pointwise c1 mainloop
    ull acc2[8][4];
#pragma unroll
    for (int j = 0; j < 8; j++)
#pragma unroll
        for (int k = 0; k < 4; k++) acc2[j][k] = 0ull;

    for (int i = 0; i < DM; i++) {
        const float* wrow = wsm + i * DM + obase;
        ulonglong2 wa = *(const ulonglong2*)(wrow);
        ulonglong2 wb = *(const ulonglong2*)(wrow + 4);
        ulonglong2 wc = *(const ulonglong2*)(wrow + 8);
        ulonglong2 we = *(const ulonglong2*)(wrow + 12);
        const float* xr = dense + i * XST + pbase;
#pragma unroll
        for (int k = 0; k < 4; k++) {
            float xv = xr[32 * k];
            ull xx = pack2(xv, xv);
            acc2[0][k] = fma2(xx, wa.x, acc2[0][k]);
            acc2[1][k] = fma2(xx, wa.y, acc2[1][k]);
            acc2[2][k] = fma2(xx, wb.x, acc2[2][k]);
            acc2[3][k] = fma2(xx, wb.y, acc2[3][k]);
            acc2[4][k] = fma2(xx, wc.x, acc2[4][k]);
            acc2[5][k] = fma2(xx, wc.y, acc2[5][k]);
            acc2[6][k] = fma2(xx, we.x, acc2[6][k]);
            acc2[7][k] = fma2(xx, we.y, acc2[7][k]);
        }
    }
    // epilogue: xs = xs + silu(acc2 + bias)
#pragma unroll
    for (int j = 0; j < 8; j++) {
        int o0 = obase + 2 * j;
        float b0 = bc1[o0], b1 = bc1[o0 + 1];
        float* d0 = xsg + o0 * PSTR;
        float* d1 = d0 + PSTR;
#pragma unroll
        for (int k = 0; k < 4; k++) {
            int p = pbase + 32 * k;
            if (p < NPIX) {
                float2 v = unpack2(acc2[j][k]);
                d0[p] = silu(v.x + b0) + d0[p];
                d1[p] = silu(v.y + b1) + d1[p];
            }
        }
    }
}

// -------- fused residual block: xs = xs + silu(w2 @ silu(w1 @ xs)) --------
__global__ __launch_bounds__(512, 1) void k_res(float* __restrict__ xsb,
                                                const float* __restrict__ wT1,
                                                const float* __restrict__ b1v,
                                                const float* __restrict__ wT2,
                                                const float* __restrict__ b2v) {
    extern __shared__ float smbuf[];
    float* dense = smbuf;             // DM*XST
    float* wsm   = smbuf + DM * XST;  // DM*DM
    int b = blockIdx.x, d = blockIdx.y;
    int tid = threadIdx.x, lane = tid & 31, wid = tid >> 5;
    float* xsg = xsb + (size_t)(d * NB + b) * DM * PSTR;

    for (int c = wid; c < DM; c += 16) {
        const float* s = xsg + c * PSTR;
        float* xq = dense + c * XST;
        for (int p = lane; p < NPIX; p += 32) xq[p] = s[p];
        if (lane < 31) xq[NPIX + lane] = 0.f;
    }
    {
        const float4* ws = (const float4*)wT1;
        float4* wd = (float4*)wsm;
#pragma unroll
        for (int j = 0; j < 8; j++) wd[tid + 512 * j] = ws[tid + 512 * j];
    }
    __syncthreads();

    const int pg    = wid >> 3;
    const int obase = (wid & 7) * 16;
    const int pbase = pg * 128 + lane;

    ull acc[8][4];
#pragma unroll
    for (int j = 0; j < 8; j++)
#pragma unroll
        for (int k = 0; k < 4; k++) acc[j][k] = 0ull;

    for (int i = 0; i < DM; i++) {
        const float* wrow = wsm + i * DM + obase;
        ulonglong2 wa = *(const ulonglong2*)(wrow);
        ulonglong2 wb = *(const ulonglong2*)(wrow + 4);
        ulonglong2 wc = *(const ulonglong2*)(wrow + 8);
        ulonglong2 we = *(const ulonglong2*)(wrow + 12);
        const float* xr = dense + i * XST + pbase;
#pragma unroll
        for (int k = 0; k < 4; k++) {
            float xv = xr[32 * k];
            ull xx = pack2(xv, xv);
            acc[0][k] = fma2(xx, wa.x, acc[0][k]);
            acc[1][k] = fma2(xx, wa.y, acc[1][k]);
            acc[2][k] = fma2(xx, wb.x, acc[2][k]);
            acc[3][k] = fma2(xx, wb.y, acc[3][k]);
            acc[4][k] = fma2(xx, wc.x, acc[4][k]);
            acc[5][k] = fma2(xx, wc.y, acc[5][k]);
            acc[6][k] = fma2(xx, we.x, acc[6][k]);
            acc[7][k] = fma2(xx, we.y, acc[7][k]);
        }
    }
    __syncthreads();   // all reads of dense + wsm done

#pragma unroll
    for (int j = 0; j < 8; j++) {
        int o0 = obase + 2 * j;
        float c0 = b1v[o0], c1 = b1v[o0 + 1];
        float* t0 = dense + o0 * XST;
        float* t1 = t0 + XST;
#pragma unroll
        for (int k = 0; k < 4; k++) {
            int p = pbase + 32 * k;
            if (p < NPIX) {
                float2 v = unpack2(acc[j][k]);
                t0[p] = silu(v.x + c0);
                t1[p] = silu(v.y + c1);
            }
        }
    }
    {
        const float4* ws = (const float4*)wT2;
        float4* wd = (float4*)wsm;
#pragma unroll
        for (int j = 0; j < 8; j++) wd[tid + 512 * j] = ws[tid + 512 * j];
    }
    __syncthreads();

    ull acc2[8][4];
#pragma unroll
    for (int j = 0; j < 8; j++)
#pragma unroll
        for (int k = 0; k < 4; k++) acc2[j][k] = 0ull;

    for (int i = 0; i < DM; i++) {
        const float* wrow = wsm + i * DM + obase;
        ulonglong2 wa = *(const ulonglong2*)(wrow);
        ulonglong2 wb = *(const ulonglong2*)(wrow + 4);
        ulonglong2 wc = *(const ulonglong2*)(wrow + 8);
        ulonglong2 we = *(const ulonglong2*)(wrow + 12);
        const float* xr = dense + i * XST + pbase;
#pragma unroll
        for (int k = 0; k < 4; k++) {
            float xv = xr[32 * k];
            ull xx = pack2(xv, xv);
            acc2[0][k] = fma2(xx, wa.x, acc2[0][k]);
            acc2[1][k] = fma2(xx, wa.y, acc2[1][k]);
            acc2[2][k] = fma2(xx, wb.x, acc2[2][k]);
            acc2[3][k] = fma2(xx, wb.y, acc2[3][k]);
            acc2[4][k] = fma2(xx, wc.x, acc2[4][k]);
            acc2[5][k] = fma2(xx, wc.y, acc2[5][k]);
            acc2[6][k] = fma2(xx, we.x, acc2[6][k]);
            acc2[7][k] = fma2(xx, we.y, acc2[7][k]);
        }
    }
#pragma unroll
    for (int j = 0; j < 8; j++) {
        int o0 = obase + 2 * j;
        float c0 = b2v[o0], c1 = b2v[o0 + 1];
        float* d0 = xsg + o0 * PSTR;
        float* d1 = d0 + PSTR;
#pragma unroll
        for (int k = 0; k < 4; k++) {
            int p = pbase + 32 * k;
            if (p < NPIX) {
                float2 v = unpack2(acc2[j][k]);
                d0[p] = silu(v.x + c0) + d0[p];
                d1[p] = silu(v.y + c1) + d1[p];
            }
        }
    }
}

// -------- fused: fin(128->64) per dir, tanh-clamp, sum dirs, prelu/4, heads --------
__global__ __launch_bounds__(256, 1) void k_fin(
    const float* __restrict__ xsb, const float* __restrict__ wT,  // [i][o] 128x64
    const float* __restrict__ bias, const float* __restrict__ prelu,
    const float* __restrict__ pdww, const float* __restrict__ pdwb,
    const float* __restrict__ ppw,
    const float* __restrict__ vl1w, const float* __restrict__ vl1b,
    const float* __restrict__ vl2w, const float* __restrict__ vl2b,
    const float* __restrict__ vlfw, const float* __restrict__ vlfb,
    const float* __restrict__ pscale, const float* __restrict__ vscale,
    float* __restrict__ out) {
    extern __shared__ float sm[];
    float* xsm  = sm;              // DM*XST
    float* facc = sm + DM * XST;   // DOUT*PADP
    __shared__ float vbuf[32], h1[32], h2[32];
    int b = blockIdx.x, tid = threadIdx.x, lane = tid & 31, wid = tid >> 5;

    for (int i = tid; i < DOUT * PADP; i += 256) facc[i] = 0.f;

    for (int d = 0; d < 4; d++) {
        __syncthreads();
        const float* src = xsb + (size_t)(d * NB + b) * DM * PSTR;
        for (int c = wid; c < DM; c += 8) {
            const float* s = src + c * PSTR;
            float* xq = xsm + c * XST;
            for (int p = lane; p < NPIX; p += 32) xq[p] = s[p];
            if (lane < 31) xq[NPIX + lane] = 0.f;
        }
        __syncthreads();

        for (int pass = 0; pass < 2; pass++) {
            int obase = pass * 32 + wid * 4;
            ull acc[4][4];
#pragma unroll
            for (int j = 0; j < 4; j++)
#pragma unroll
                for (int k = 0; k < 4; k++) acc[j][k] = 0ull;

#pragma unroll 4
            for (int i = 0; i < DM; i++) {
                float4 wv = *(const float4*)(wT + i * DOUT + obase);
                ull w0 = pack2(wv.x, wv.x), w1 = pack2(wv.y, wv.y);
                ull w2 = pack2(wv.z, wv.z), w3 = pack2(wv.w, wv.w);
                const ull* xr = (const ull*)(xsm + i * XST) + lane;
#pragma unroll
                for (int k = 0; k < 4; k++) {
                    ull xx = xr[32 * k];
                    acc[0][k] = fma2(xx, w0, acc[0][k]);
                    acc[1][k] = fma2(xx, w1, acc[1][k]);
                    acc[2][k] = fma2(xx, w2, acc[2][k]);
                    acc[3][k] = fma2(xx, w3, acc[3][k]);
                }
            }
#pragma unroll
            for (int j = 0; j < 4; j++) {
                int o = obase + j;
                float bv = bias[o];
                float* fo = facc + o * PADP;
#pragma unroll
                for (int k = 0; k < 4; k++) {
                    int px = 2 * (lane + 32 * k);
                    float2 v = unpack2(acc[j][k]);
                    if (px < NPIX) {
                        int h = px / 15, w = px - h * 15;
                        fo[(h + 1) * 17 + w + 1] += MAXF * tanhf((v.x + bv) * INV_MAXF);
                    }
                    if (px + 1 < NPIX) {
                        int h = (px + 1) / 15, w = (px + 1) - h * 15;
                        fo[(h + 1) * 17 + w + 1] += MAXF * tanhf((v.y + bv) * INV_MAXF);
                    }
                }
            }
        }
    }
    __syncthreads();

    // prelu + /4
    for (int idx = tid; idx < DOUT * NPIX; idx += 256) {
        int o = idx / NPIX, p = idx - o * NPIX;
        int h = p / 15, w = p - h * 15;
        float* fp = &facc[o * PADP + (h + 1) * 17 + w + 1];
        float v = *fp;
        *fp = (v >= 0.f ? v : prelu[o] * v) * 0.25f;
    }
    __syncthreads();

    // policy head
    if (tid < NPIX) {
        int h = tid / 15, w = tid - h * 15;
        int base = (h + 1) * 17 + (w + 1);
        float acc = 0.f;
        for (int c = 0; c < DP; c++) {
            const float* fc = facc + c * PADP + base;
            const float* wk = pdww + c * 9;
            float s = pdwb[c];
#pragma unroll
            for (int r = 0; r < 3; r++)
#pragma unroll
                for (int cc = 0; cc < 3; cc++)
                    s += wk[r * 3 + cc] * fc[(r - 1) * 17 + (cc - 1)];
            s = (s >= 0.f) ? s : s * 0.0625f;
            s = fminf(fmaxf(s, -MAXF), MAXF);
            acc += ppw[c] * s;
        }
        acc = (acc >= 0.f) ? acc : acc * 0.0625f;
        out[NB * 3 + (size_t)b * NPIX + tid] = acc * pscale[0];
    }
    __syncthreads();

    // value head (warp 0)
    if (wid == 0) {
        const float* fc = facc + (DP + lane) * PADP;
        float s = 0.f;
        for (int h = 0; h < 15; h++)
#pragma unroll
            for (int w = 0; w < 15; w++) s += fc[(h + 1) * 17 + w + 1];
        vbuf[lane] = fmaxf(s * (1.f / 225.f), 0.f);
        __syncwarp();
        float a = vl1b[lane];
        for (int i = 0; i < 32; i++) a += vl1w[lane * 32 + i] * vbuf[i];
        h1[lane] = fminf(fmaxf(a, 0.f), MAXM);
        __syncwarp();
        float g = vl2b[lane];
        for (int i = 0; i < 32; i++) g += vl2w[lane * 32 + i] * h1[i];
        h2[lane] = fminf(fmaxf(g, 0.f), MAXM);
        __syncwarp();
        if (lane < 3) {
            float o = vlfb[lane];
            for (int i = 0; i < 32; i++) o += vlfw[lane * 32 + i] * h2[i];
            out[(size_t)b * 3 + lane] = o * vscale[0];
        }
    }
}

// ---------------- host ----------------
extern "C" void kernel_launch(void* const* d_in, const int* in_sizes, int n_in,
                              void* d_out, int out_size) {
    const float* x       = (const float*)d_in[0];
    const float* map_w   = (const float*)d_in[1];
    const float* map_b   = (const float*)d_in[2];
    const float* dconv_w = (const float*)d_in[3];
    const float* dconv_b = (const float*)d_in[4];
    const float* c1_w    = (const float*)d_in[5];
    const float* c1_b    = (const float*)d_in[6];
    const float* r0_w1   = (const float*)d_in[7];
    const float* r0_b1   = (const float*)d_in[8];
    const float* r0_w2   = (const float*)d_in[9];
    const float* r0_b2   = (const float*)d_in[10];
    const float* fin_w   = (const float*)d_in[11];
    const float* fin_b   = (const float*)d_in[12];
    const float* prelu_w = (const float*)d_in[13];
    const float* pdw_w   = (const float*)d_in[14];
    const float* pdw_b   = (const float*)d_in[15];
    const float* ppw_w   = (const float*)d_in[16];
    const float* vl1_w   = (const float*)d_in[17];
    const float* vl1_b   = (const float*)d_in[18];
    const float* vl2_w   = (const float*)d_in[19];
    const float* vl2_b   = (const float*)d_in[20];
    const float* vlf_w   = (const float*)d_in[21];
    const float* vlf_b   = (const float*)d_in[22];
    const float* pscale  = (const float*)d_in[23];
    const float* vscale  = (const float*)d_in[24];
    float* out = (float*)d_out;

    float *xs, *wdc, *wc1, *wr1, *wr2, *wfn;
    cudaGetSymbolAddress((void**)&xs,  g_xs);
    cudaGetSymbolAddress((void**)&wdc, g_wdc);
    cudaGetSymbolAddress((void**)&wc1, g_wc1);
    cudaGetSymbolAddress((void**)&wr1, g_wr1);
    cudaGetSymbolAddress((void**)&wr2, g_wr2);
    cudaGetSymbolAddress((void**)&wfn, g_wfn);

    cudaFuncSetAttribute(k_layer, cudaFuncAttributeMaxDynamicSharedMemorySize, SMA);
    cudaFuncSetAttribute(k_res,   cudaFuncAttributeMaxDynamicSharedMemorySize, SMB);
    cudaFuncSetAttribute(k_fin,   cudaFuncAttributeMaxDynamicSharedMemorySize, SMC);

    // launches 1-2: weight transposes (ncu -s 5 lands on a k_layer)
    k_xpose<<<256, 256>>>(dconv_w, wdc, 12, DM, DM);
    k_xpose_rest<<<128, 256>>>(c1_w, r0_w1, r0_w2, fin_w, wc1, wr1, wr2, wfn);

    dim3 gbd(NB, 4);
    k_map<<<gbd, 256>>>(x, map_w, map_b, xs);
    for (int l = 0; l < 4; l++)
        k_layer<<<gbd, 512, SMA>>>(xs, wdc + l * 3 * DM * DM, dconv_b + l * DM,
                                   wc1 + l * DM * DM, c1_b + l * DM);
    k_res<<<gbd, 512, SMB>>>(xs, wr1, r0_b1, wr2, r0_b2);

    k_fin<<<NB, 256, SMC>>>(xs, wfn, fin_b, prelu_w, pdw_w, pdw_b, ppw_w,
                            vl1_w, vl1_b, vl2_w, vl2_b, vlf_w, vlf_b,
                            pscale, vscale, out);
}

// round 10
// speedup vs baseline: 1.4242x; 1.4242x over previous
#include <cuda_runtime.h>
#include <math.h>

typedef unsigned long long ull;

#define NB   512
#define DM   128
#define DOUT 64
#define DP   32
#define NPIX 225
#define PSTR 228          // global per-channel pixel stride (floats)
#define PADP 292          // padded 17x17 (289) channel stride in smem
#define XST  256          // smem dense pixel stride
#define MAXF 31.75f
#define INV_MAXF (1.0f/31.75f)
#define MAXM (127.0f/3.515625f)

#define SMA ((DM*PADP + DM*DM)*4)     // k_dirconv smem: activations + 1-tap weights
#define SMB ((DM*XST  + DM*DM)*4)     // k_pw smem: activations + weights
#define SMC (DM*XST*4 + DOUT*PADP*4)  // k_fin smem

// ---------------- device scratch (no allocation) ----------------
__device__ __align__(16) float g_xs [4ull*NB*DM*PSTR];
__device__ __align__(16) float g_tmp[4ull*NB*DM*PSTR];
__device__ __align__(16) float g_wdc[12*DM*DM];   // dconv  [l*3+t][i][o]
__device__ __align__(16) float g_wc1[4*DM*DM];    // c1     [l][i][o]
__device__ __align__(16) float g_wr1[DM*DM];      // r0_w1  [i][o]
__device__ __align__(16) float g_wr2[DM*DM];      // r0_w2  [i][o]
__device__ __align__(16) float g_wfn[DM*DOUT];    // fin    [i][o]

// tap offsets (dr,dc): tap t reads x[h+dr][w+dc]
__constant__ int c_dr[4][3] = {{0,0,0},{-1,0,1},{-1,0,1},{1,0,-1}};
__constant__ int c_dc[4][3] = {{-1,0,1},{0,0,0},{-1,0,1},{-1,0,1}};

// ---------------- f32x2 helpers ----------------
__device__ __forceinline__ ull pack2(float lo, float hi) {
    ull r; asm("mov.b64 %0, {%1,%2};" : "=l"(r) : "f"(lo), "f"(hi)); return r;
}
__device__ __forceinline__ float2 unpack2(ull v) {
    float2 f; asm("mov.b64 {%0,%1}, %2;" : "=f"(f.x), "=f"(f.y) : "l"(v)); return f;
}
__device__ __forceinline__ ull fma2(ull a, ull b, ull c) {
    ull d; asm("fma.rn.f32x2 %0, %1, %2, %3;" : "=l"(d) : "l"(a), "l"(b), "l"(c)); return d;
}
__device__ __forceinline__ float silu(float x) {
    return __fdividef(x, 1.f + __expf(-x));
}

// ---------------- transpose: dconv [12][o][i] -> [12][i][o] ----------------
__global__ void k_xpose(const float* __restrict__ src, float* __restrict__ dst,
                        int nmat, int R, int C) {
    int n = nmat * R * C;
    for (int idx = blockIdx.x * blockDim.x + threadIdx.x; idx < n;
         idx += gridDim.x * blockDim.x) {
        int m = idx / (R * C);
        int rem = idx - m * R * C;
        int r = rem / C, c = rem - r * C;
        dst[(m * C + c) * R + r] = src[idx];
    }
}

// ---------------- transpose the remaining 4 weight families in ONE launch ----------------
__global__ void k_xpose_rest(const float* __restrict__ c1,
                             const float* __restrict__ r1,
                             const float* __restrict__ r2,
                             const float* __restrict__ fin,
                             float* __restrict__ wc1, float* __restrict__ wr1,
                             float* __restrict__ wr2, float* __restrict__ wfn) {
    const int N1 = 4 * DM * DM;
    const int N2 = N1 + DM * DM;
    const int N3 = N2 + DM * DM;
    const int N4 = N3 + DOUT * DM;
    for (int idx = blockIdx.x * blockDim.x + threadIdx.x; idx < N4;
         idx += gridDim.x * blockDim.x) {
        if (idx < N1) {
            int m = idx / (DM * DM);
            int rem = idx - m * DM * DM;
            int r = rem / DM, c = rem - r * DM;
            wc1[(m * DM + c) * DM + r] = c1[idx];
        } else if (idx < N2) {
            int i2 = idx - N1;
            int r = i2 / DM, c = i2 - r * DM;
            wr1[c * DM + r] = r1[i2];
        } else if (idx < N3) {
            int i2 = idx - N2;
            int r = i2 / DM, c = i2 - r * DM;
            wr2[c * DM + r] = r2[i2];
        } else {
            int i2 = idx - N3;
            int r = i2 / DM, c = i2 - r * DM;  // r = o (64), c = i (128)
            wfn[c * DOUT + r] = fin[i2];
        }
    }
}

// ---------------- input map conv (2 -> 128) + silu ----------------
__global__ __launch_bounds__(256) void k_map(const float* __restrict__ x,
                                             const float* __restrict__ mw,
                                             const float* __restrict__ mb,
                                             float* __restrict__ xsb) {
    int b = blockIdx.x, d = blockIdx.y, tid = threadIdx.x;
    __shared__ float xp[2 * PADP];
    for (int i = tid; i < 2 * PADP; i += 256) xp[i] = 0.f;
    __syncthreads();
    const float* xb = x + (size_t)b * 2 * NPIX;
    for (int i = tid; i < 2 * NPIX; i += 256) {
        int c = i / NPIX, p = i - c * NPIX;
        int h = p / 15, w = p - h * 15;
        xp[c * PADP + (h + 1) * 17 + (w + 1)] = xb[i];
    }
    __syncthreads();
    int dr[3], dc[3];
#pragma unroll
    for (int t = 0; t < 3; t++) { dr[t] = c_dr[d][t]; dc[t] = c_dc[d][t]; }
    float* dst = xsb + (size_t)(d * NB + b) * DM * PSTR;
    for (int idx = tid; idx < DM * NPIX; idx += 256) {
        int o = idx / NPIX, p = idx - o * NPIX;
        int h = p / 15, w = p - h * 15;
        float acc = mb[o];
#pragma unroll
        for (int t = 0; t < 3; t++) {
            int off = (h + 1 + dr[t]) * 17 + (w + 1 + dc[t]);
            acc += mw[(t * DM + o) * 2 + 0] * xp[off]
                 + mw[(t * DM + o) * 2 + 1] * xp[PADP + off];
        }
        dst[o * PSTR + p] = silu(acc);
    }
}

// -------- directional 3-tap conv 128->128 + silu --------
// 512 threads / 16 warps. Warp = (pixel-group, o-group): 8 o-groups of 16
// channels x 2 pixel-groups of 128 px. Per (i,t): 4 uniform LDS.128 (w) +
// 4 scalar LDS (x) = 8 wavefronts for 32 FMA2 -> 4:1, FMA/L1 balanced.
__global__ __launch_bounds__(512, 1) void k_dirconv(const float* __restrict__ srcb,
                                                    float* __restrict__ dstb,
                                                    const float* __restrict__ wT, // [3][i][o]
                                                    const float* __restrict__ bias) {
    extern __shared__ float smbuf[];
    float* xpad = smbuf;              // DM*PADP
    float* wsm  = smbuf + DM * PADP;  // DM*DM (one tap)
    int b = blockIdx.x, d = blockIdx.y;
    int tid = threadIdx.x, lane = tid & 31, wid = tid >> 5;
    const float* src = srcb + (size_t)(d * NB + b) * DM * PSTR;
    float*       dst = dstb + (size_t)(d * NB + b) * DM * PSTR;

    for (int i = tid; i < DM * PADP; i += 512) xpad[i] = 0.f;
    __syncthreads();
    for (int c = wid; c < DM; c += 16) {
        const float* s = src + c * PSTR;
        float* xq = xpad + c * PADP;
        for (int p = lane; p < NPIX; p += 32) {
            int h = p / 15, w = p - h * 15;
            xq[(h + 1) * 17 + (w + 1)] = s[p];
        }
    }

    const int pg    = wid >> 3;         // pixel group 0/1
    const int obase = (wid & 7) * 16;   // warp's 16 output channels

    int offs[3][4];
#pragma unroll
    for (int k = 0; k < 4; k++) {
        int p = pg * 128 + lane + 32 * k;
        int pv = (p < NPIX) ? p : 0;
        int h = pv / 15, w = pv - h * 15;
#pragma unroll
        for (int t = 0; t < 3; t++)
            offs[t][k] = (h + 1 + c_dr[d][t]) * 17 + (w + 1 + c_dc[d][t]);
    }

    ull acc[8][4];
#pragma unroll
    for (int j = 0; j < 8; j++)
#pragma unroll
        for (int k = 0; k < 4; k++) acc[j][k] = 0ull;

    for (int t = 0; t < 3; t++) {
        __syncthreads();   // protect wsm from readers of the previous tap
        {
            const float4* ws = (const float4*)(wT + t * DM * DM);
            float4* wd = (float4*)wsm;
#pragma unroll
            for (int j = 0; j < 8; j++) wd[tid + 512 * j] = ws[tid + 512 * j];
        }
        __syncthreads();

#pragma unroll 2
        for (int i = 0; i < DM; i++) {
            const float* xr = xpad + i * PADP;
            const float* wrow = wsm + i * DM + obase;
            ulonglong2 wa = *(const ulonglong2*)(wrow);
            ulonglong2 wb = *(const ulonglong2*)(wrow + 4);
            ulonglong2 wc = *(const ulonglong2*)(wrow + 8);
            ulonglong2 we = *(const ulonglong2*)(wrow + 12);
#pragma unroll
            for (int k = 0; k < 4; k++) {
                float xv = xr[offs[t][k]];
                ull xx = pack2(xv, xv);
                acc[0][k] = fma2(xx, wa.x, acc[0][k]);
                acc[1][k] = fma2(xx, wa.y, acc[1][k]);
                acc[2][k] = fma2(xx, wb.x, acc[2][k]);
                acc[3][k] = fma2(xx, wb.y, acc[3][k]);
                acc[4][k] = fma2(xx, wc.x, acc[4][k]);
                acc[5][k] = fma2(xx, wc.y, acc[5][k]);
                acc[6][k] = fma2(xx, we.x, acc[6][k]);
                acc[7][k] = fma2(xx, we.y, acc[7][k]);
            }
        }
    }
#pragma unroll
    for (int j = 0; j < 8; j++) {
        int o0 = obase + 2 * j;
        float b0 = bias[o0], b1 = bias[o0 + 1];
        float* d0 = dst + o0 * PSTR;
        float* d1 = d0 + PSTR;
#pragma unroll
        for (int k = 0; k < 4; k++) {
            int p = pg * 128 + lane + 32 * k;
            if (p < NPIX) {
                float2 v = unpack2(acc[j][k]);
                d0[p] = silu(v.x + b0);
                d1[p] = silu(v.y + b1);
            }
        }
    }
}

// -------- pointwise 128->128 + silu; ADD=1: dst = dst + silu(pw(src)) --------
// Same 16-o-per-warp structure; weights staged once.
template <int ADD>
__global__ __launch_bounds__(512, 1) void k_pw(const float* __restrict__ srcb,
                                               const float* __restrict__ wT,  // [i][o]
                                               const float* __restrict__ bias,
                                               float* __restrict__ dstb) {
    extern __shared__ float smbuf[];
    float* xsm = smbuf;              // DM*XST
    float* wsm = smbuf + DM * XST;   // DM*DM
    int b = blockIdx.x, d = blockIdx.y;
    int tid = threadIdx.x, lane = tid & 31, wid = tid >> 5;
    const float* src = srcb + (size_t)(d * NB + b) * DM * PSTR;
    float*       dst = dstb + (size_t)(d * NB + b) * DM * PSTR;

    for (int c = wid; c < DM; c += 16) {
        const float* s = src + c * PSTR;
        float* xq = xsm + c * XST;
        for (int p = lane; p < NPIX; p += 32) xq[p] = s[p];
        if (lane < 31) xq[NPIX + lane] = 0.f;
    }
    {
        const float4* ws = (const float4*)wT;
        float4* wd = (float4*)wsm;
#pragma unroll
        for (int j = 0; j < 8; j++) wd[tid + 512 * j] = ws[tid + 512 * j];
    }
    __syncthreads();

    const int pg    = wid >> 3;
    const int obase = (wid & 7) * 16;
    const int pbase = pg * 128 + lane;

    ull acc[8][4];
#pragma unroll
    for (int j = 0; j < 8; j++)
#pragma unroll
        for (int k = 0; k < 4; k++) acc[j][k] = 0ull;

#pragma unroll 2
    for (int i = 0; i < DM; i++) {
        const float* wrow = wsm + i * DM + obase;
        ulonglong2 wa = *(const ulonglong2*)(wrow);
        ulonglong2 wb = *(const ulonglong2*)(wrow + 4);
        ulonglong2 wc = *(const ulonglong2*)(wrow + 8);
        ulonglong2 we = *(const ulonglong2*)(wrow + 12);
        const float* xr = xsm + i * XST + pbase;
#pragma unroll
        for (int k = 0; k < 4; k++) {
            float xv = xr[32 * k];
            ull xx = pack2(xv, xv);
            acc[0][k] = fma2(xx, wa.x, acc[0][k]);
            acc[1][k] = fma2(xx, wa.y, acc[1][k]);
            acc[2][k] = fma2(xx, wb.x, acc[2][k]);
            acc[3][k] = fma2(xx, wb.y, acc[3][k]);
            acc[4][k] = fma2(xx, wc.x, acc[4][k]);
            acc[5][k] = fma2(xx, wc.y, acc[5][k]);
            acc[6][k] = fma2(xx, we.x, acc[6][k]);
            acc[7][k] = fma2(xx, we.y, acc[7][k]);
        }
    }
#pragma unroll
    for (int j = 0; j < 8; j++) {
        int o0 = obase + 2 * j;
        float b0 = bias[o0], b1 = bias[o0 + 1];
        float* d0 = dst + o0 * PSTR;
        float* d1 = d0 + PSTR;
#pragma unroll
        for (int k = 0; k < 4; k++) {
            int p = pbase + 32 * k;
            if (p < NPIX) {
                float2 v = unpack2(acc[j][k]);
                float y0 = silu(v.x + b0), y1 = silu(v.y + b1);
                if (ADD) { y0 += d0[p]; y1 += d1[p]; }
                d0[p] = y0;
                d1[p] = y1;
            }
        }
    }
}

// -------- fused: fin(128->64) per dir, tanh-clamp, sum dirs, prelu/4, heads --------
__global__ __launch_bounds__(256, 1) void k_fin(
    const float* __restrict__ xsb, const float* __restrict__ wT,  // [i][o] 128x64
    const float* __restrict__ bias, const float* __restrict__ prelu,
    const float* __restrict__ pdww, const float* __restrict__ pdwb,
    const float* __restrict__ ppw,
    const float* __restrict__ vl1w, const float* __restrict__ vl1b,
    const float* __restrict__ vl2w, const float* __restrict__ vl2b,
    const float* __restrict__ vlfw, const float* __restrict__ vlfb,
    const float* __restrict__ pscale, const float* __restrict__ vscale,
    float* __restrict__ out) {
    extern __shared__ float sm[];
    float* xsm  = sm;              // DM*XST
    float* facc = sm + DM * XST;   // DOUT*PADP
    __shared__ float vbuf[32], h1[32], h2[32];
    int b = blockIdx.x, tid = threadIdx.x, lane = tid & 31, wid = tid >> 5;

    for (int i = tid; i < DOUT * PADP; i += 256) facc[i] = 0.f;

    for (int d = 0; d < 4; d++) {
        __syncthreads();
        const float* src = xsb + (size_t)(d * NB + b) * DM * PSTR;
        for (int c = wid; c < DM; c += 8) {
            const float* s = src + c * PSTR;
            float* xq = xsm + c * XST;
            for (int p = lane; p < NPIX; p += 32) xq[p] = s[p];
            if (lane < 31) xq[NPIX + lane] = 0.f;
        }
        __syncthreads();

        for (int pass = 0; pass < 2; pass++) {
            int obase = pass * 32 + wid * 4;
            ull acc[4][4];
#pragma unroll
            for (int j = 0; j < 4; j++)
#pragma unroll
                for (int k = 0; k < 4; k++) acc[j][k] = 0ull;

#pragma unroll 4
            for (int i = 0; i < DM; i++) {
                float4 wv = *(const float4*)(wT + i * DOUT + obase);
                ull w0 = pack2(wv.x, wv.x), w1 = pack2(wv.y, wv.y);
                ull w2 = pack2(wv.z, wv.z), w3 = pack2(wv.w, wv.w);
                const ull* xr = (const ull*)(xsm + i * XST) + lane;
#pragma unroll
                for (int k = 0; k < 4; k++) {
                    ull xx = xr[32 * k];
                    acc[0][k] = fma2(xx, w0, acc[0][k]);
                    acc[1][k] = fma2(xx, w1, acc[1][k]);
                    acc[2][k] = fma2(xx, w2, acc[2][k]);
                    acc[3][k] = fma2(xx, w3, acc[3][k]);
                }
            }
#pragma unroll
            for (int j = 0; j < 4; j++) {
                int o = obase + j;
                float bv = bias[o];
                float* fo = facc + o * PADP;
#pragma unroll
                for (int k = 0; k < 4; k++) {
                    int px = 2 * (lane + 32 * k);
                    float2 v = unpack2(acc[j][k]);
                    if (px < NPIX) {
                        int h = px / 15, w = px - h * 15;
                        fo[(h + 1) * 17 + w + 1] += MAXF * tanhf((v.x + bv) * INV_MAXF);
                    }
                    if (px + 1 < NPIX) {
                        int h = (px + 1) / 15, w = (px + 1) - h * 15;
                        fo[(h + 1) * 17 + w + 1] += MAXF * tanhf((v.y + bv) * INV_MAXF);
                    }
                }
            }
        }
    }
    __syncthreads();

    // prelu + /4
    for (int idx = tid; idx < DOUT * NPIX; idx += 256) {
        int o = idx / NPIX, p = idx - o * NPIX;
        int h = p / 15, w = p - h * 15;
        float* fp = &facc[o * PADP + (h + 1) * 17 + w + 1];
        float v = *fp;
        *fp = (v >= 0.f ? v : prelu[o] * v) * 0.25f;
    }
    __syncthreads();

    // policy head
    if (tid < NPIX) {
        int h = tid / 15, w = tid - h * 15;
        int base = (h + 1) * 17 + (w + 1);
        float acc = 0.f;
        for (int c = 0; c < DP; c++) {
            const float* fc = facc + c * PADP + base;
            const float* wk = pdww + c * 9;
            float s = pdwb[c];
#pragma unroll
            for (int r = 0; r < 3; r++)
#pragma unroll
                for (int cc = 0; cc < 3; cc++)
                    s += wk[r * 3 + cc] * fc[(r - 1) * 17 + (cc - 1)];
            s = (s >= 0.f) ? s : s * 0.0625f;
            s = fminf(fmaxf(s, -MAXF), MAXF);
            acc += ppw[c] * s;
        }
        acc = (acc >= 0.f) ? acc : acc * 0.0625f;
        out[NB * 3 + (size_t)b * NPIX + tid] = acc * pscale[0];
    }
    __syncthreads();

    // value head (warp 0)
    if (wid == 0) {
        const float* fc = facc + (DP + lane) * PADP;
        float s = 0.f;
        for (int h = 0; h < 15; h++)
#pragma unroll
            for (int w = 0; w < 15; w++) s += fc[(h + 1) * 17 + w + 1];
        vbuf[lane] = fmaxf(s * (1.f / 225.f), 0.f);
        __syncwarp();
        float a = vl1b[lane];
        for (int i = 0; i < 32; i++) a += vl1w[lane * 32 + i] * vbuf[i];
        h1[lane] = fminf(fmaxf(a, 0.f), MAXM);
        __syncwarp();
        float g = vl2b[lane];
        for (int i = 0; i < 32; i++) g += vl2w[lane * 32 + i] * h1[i];
        h2[lane] = fminf(fmaxf(g, 0.f), MAXM);
        __syncwarp();
        if (lane < 3) {
            float o = vlfb[lane];
            for (int i = 0; i < 32; i++) o += vlfw[lane * 32 + i] * h2[i];
            out[(size_t)b * 3 + lane] = o * vscale[0];
        }
    }
}

// ---------------- host ----------------
extern "C" void kernel_launch(void* const* d_in, const int* in_sizes, int n_in,
                              void* d_out, int out_size) {
    const float* x       = (const float*)d_in[0];
    const float* map_w   = (const float*)d_in[1];
    const float* map_b   = (const float*)d_in[2];
    const float* dconv_w = (const float*)d_in[3];
    const float* dconv_b = (const float*)d_in[4];
    const float* c1_w    = (const float*)d_in[5];
    const float* c1_b    = (const float*)d_in[6];
    const float* r0_w1   = (const float*)d_in[7];
    const float* r0_b1   = (const float*)d_in[8];
    const float* r0_w2   = (const float*)d_in[9];
    const float* r0_b2   = (const float*)d_in[10];
    const float* fin_w   = (const float*)d_in[11];
    const float* fin_b   = (const float*)d_in[12];
    const float* prelu_w = (const float*)d_in[13];
    const float* pdw_w   = (const float*)d_in[14];
    const float* pdw_b   = (const float*)d_in[15];
    const float* ppw_w   = (const float*)d_in[16];
    const float* vl1_w   = (const float*)d_in[17];
    const float* vl1_b   = (const float*)d_in[18];
    const float* vl2_w   = (const float*)d_in[19];
    const float* vl2_b   = (const float*)d_in[20];
    const float* vlf_w   = (const float*)d_in[21];
    const float* vlf_b   = (const float*)d_in[22];
    const float* pscale  = (const float*)d_in[23];
    const float* vscale  = (const float*)d_in[24];
    float* out = (float*)d_out;

    float *xs, *tmp, *wdc, *wc1, *wr1, *wr2, *wfn;
    cudaGetSymbolAddress((void**)&xs,  g_xs);
    cudaGetSymbolAddress((void**)&tmp, g_tmp);
    cudaGetSymbolAddress((void**)&wdc, g_wdc);
    cudaGetSymbolAddress((void**)&wc1, g_wc1);
    cudaGetSymbolAddress((void**)&wr1, g_wr1);
    cudaGetSymbolAddress((void**)&wr2, g_wr2);
    cudaGetSymbolAddress((void**)&wfn, g_wfn);

    cudaFuncSetAttribute(k_dirconv, cudaFuncAttributeMaxDynamicSharedMemorySize, SMA);
    cudaFuncSetAttribute(k_pw<0>,   cudaFuncAttributeMaxDynamicSharedMemorySize, SMB);
    cudaFuncSetAttribute(k_pw<1>,   cudaFuncAttributeMaxDynamicSharedMemorySize, SMB);
    cudaFuncSetAttribute(k_fin,     cudaFuncAttributeMaxDynamicSharedMemorySize, SMC);

    // launches 1-2: weight transposes (ncu -s 5 lands on k_dirconv layer 1)
    k_xpose<<<256, 256>>>(dconv_w, wdc, 12, DM, DM);
    k_xpose_rest<<<128, 256>>>(c1_w, r0_w1, r0_w2, fin_w, wc1, wr1, wr2, wfn);

    dim3 gbd(NB, 4);
    k_map<<<gbd, 256>>>(x, map_w, map_b, xs);
    for (int l = 0; l < 4; l++) {
        k_dirconv<<<gbd, 512, SMA>>>(xs, tmp, wdc + l * 3 * DM * DM,
                                     dconv_b + l * DM);
        k_pw<1><<<gbd, 512, SMB>>>(tmp, wc1 + l * DM * DM, c1_b + l * DM, xs);
    }
    k_pw<0><<<gbd, 512, SMB>>>(xs, wr1, r0_b1, tmp);
    k_pw<1><<<gbd, 512, SMB>>>(tmp, wr2, r0_b2, xs);

    k_fin<<<NB, 256, SMC>>>(xs, wfn, fin_b, prelu_w, pdw_w, pdw_b, ppw_w,
                            vl1_w, vl1_b, vl2_w, vl2_b, vlf_w, vlf_b,
                            pscale, vscale, out);
}

// round 11
// speedup vs baseline: 1.9521x; 1.3707x over previous
#include <cuda_runtime.h>
#include <cuda_bf16.h>
#include <math.h>

typedef unsigned long long ull;
typedef unsigned int uint;

#define NB   512
#define DM   128
#define DOUT 64
#define DP   32
#define NPIX 225
#define PSTR 228
#define PADP 292
#define XST  256
#define MAXF 31.75f
#define INV_MAXF (1.0f/31.75f)
#define MAXM (127.0f/3.515625f)

// mma dirconv smem layout
#define XROWB 272                      // bytes per xT row (136 bf16)
#define XROWS 289                      // padded 17x17 pixels
#define XT_BYTES (XROWS*XROWB)         // 78608
#define WROWB 272
#define WT_BYTES (128*WROWB)           // 34816
#define SMD (2*XT_BYTES + 2*WT_BYTES)  // 226848

#define SMB ((DM*XST + DM*DM)*4)       // k_pw smem
#define SMC (DM*XST*4 + DOUT*PADP*4)   // k_fin smem

// ---------------- device scratch ----------------
__device__ __align__(16) float g_xs [4ull*NB*DM*PSTR];
__device__ __align__(16) float g_tmp[4ull*NB*DM*PSTR];
__device__ __align__(16) __nv_bfloat16 g_wdch[12*128*136];  // dconv hi [l*3+t][o][136]
__device__ __align__(16) __nv_bfloat16 g_wdcl[12*128*136];  // dconv lo
__device__ __align__(16) float g_wc1[4*DM*DM];    // c1     [l][i][o]
__device__ __align__(16) float g_wr1[DM*DM];
__device__ __align__(16) float g_wr2[DM*DM];
__device__ __align__(16) float g_wfn[DM*DOUT];

__constant__ int c_dr[4][3] = {{0,0,0},{-1,0,1},{-1,0,1},{1,0,-1}};
__constant__ int c_dc[4][3] = {{-1,0,1},{0,0,0},{-1,0,1},{-1,0,1}};

// ---------------- helpers ----------------
__device__ __forceinline__ ull pack2(float lo, float hi) {
    ull r; asm("mov.b64 %0, {%1,%2};" : "=l"(r) : "f"(lo), "f"(hi)); return r;
}
__device__ __forceinline__ float2 unpack2(ull v) {
    float2 f; asm("mov.b64 {%0,%1}, %2;" : "=f"(f.x), "=f"(f.y) : "l"(v)); return f;
}
__device__ __forceinline__ ull fma2(ull a, ull b, ull c) {
    ull d; asm("fma.rn.f32x2 %0, %1, %2, %3;" : "=l"(d) : "l"(a), "l"(b), "l"(c)); return d;
}
__device__ __forceinline__ float silu(float x) {
    return __fdividef(x, 1.f + __expf(-x));
}
__device__ __forceinline__ void mma_bf16(float* c,
    uint a0, uint a1, uint a2, uint a3, uint b0, uint b1) {
    asm("mma.sync.aligned.m16n8k16.row.col.f32.bf16.bf16.f32 "
        "{%0,%1,%2,%3}, {%4,%5,%6,%7}, {%8,%9}, {%0,%1,%2,%3};"
        : "+f"(c[0]), "+f"(c[1]), "+f"(c[2]), "+f"(c[3])
        : "r"(a0), "r"(a1), "r"(a2), "r"(a3), "r"(b0), "r"(b1));
}

// ---------------- dconv weight prep: f32 [12][o][128] -> bf16 hi/lo [12][o][136] ----------------
__global__ void k_prep_dconv(const float* __restrict__ w,
                             __nv_bfloat16* __restrict__ wh,
                             __nv_bfloat16* __restrict__ wl) {
    int n = 12 * 128 * 136;
    for (int idx = blockIdx.x * blockDim.x + threadIdx.x; idx < n;
         idx += gridDim.x * blockDim.x) {
        int m = idx / (128 * 136);
        int rem = idx - m * 128 * 136;
        int o = rem / 136, i = rem - o * 136;
        float v = (i < 128) ? w[(m * 128 + o) * 128 + i] : 0.f;
        __nv_bfloat16 hi = __float2bfloat16(v);
        wh[idx] = hi;
        wl[idx] = __float2bfloat16(v - __bfloat162float(hi));
    }
}

// ---------------- transpose pw weight families (one launch) ----------------
__global__ void k_xpose_rest(const float* __restrict__ c1,
                             const float* __restrict__ r1,
                             const float* __restrict__ r2,
                             const float* __restrict__ fin,
                             float* __restrict__ wc1, float* __restrict__ wr1,
                             float* __restrict__ wr2, float* __restrict__ wfn) {
    const int N1 = 4 * DM * DM;
    const int N2 = N1 + DM * DM;
    const int N3 = N2 + DM * DM;
    const int N4 = N3 + DOUT * DM;
    for (int idx = blockIdx.x * blockDim.x + threadIdx.x; idx < N4;
         idx += gridDim.x * blockDim.x) {
        if (idx < N1) {
            int m = idx / (DM * DM);
            int rem = idx - m * DM * DM;
            int r = rem / DM, c = rem - r * DM;
            wc1[(m * DM + c) * DM + r] = c1[idx];
        } else if (idx < N2) {
            int i2 = idx - N1;
            int r = i2 / DM, c = i2 - r * DM;
            wr1[c * DM + r] = r1[i2];
        } else if (idx < N3) {
            int i2 = idx - N2;
            int r = i2 / DM, c = i2 - r * DM;
            wr2[c * DM + r] = r2[i2];
        } else {
            int i2 = idx - N3;
            int r = i2 / DM, c = i2 - r * DM;
            wfn[c * DOUT + r] = fin[i2];
        }
    }
}

// ---------------- input map conv (2 -> 128) + silu ----------------
__global__ __launch_bounds__(256) void k_map(const float* __restrict__ x,
                                             const float* __restrict__ mw,
                                             const float* __restrict__ mb,
                                             float* __restrict__ xsb) {
    int b = blockIdx.x, d = blockIdx.y, tid = threadIdx.x;
    __shared__ float xp[2 * PADP];
    for (int i = tid; i < 2 * PADP; i += 256) xp[i] = 0.f;
    __syncthreads();
    const float* xb = x + (size_t)b * 2 * NPIX;
    for (int i = tid; i < 2 * NPIX; i += 256) {
        int c = i / NPIX, p = i - c * NPIX;
        int h = p / 15, w = p - h * 15;
        xp[c * PADP + (h + 1) * 17 + (w + 1)] = xb[i];
    }
    __syncthreads();
    int dr[3], dc[3];
#pragma unroll
    for (int t = 0; t < 3; t++) { dr[t] = c_dr[d][t]; dc[t] = c_dc[d][t]; }
    float* dst = xsb + (size_t)(d * NB + b) * DM * PSTR;
    for (int idx = tid; idx < DM * NPIX; idx += 256) {
        int o = idx / NPIX, p = idx - o * NPIX;
        int h = p / 15, w = p - h * 15;
        float acc = mb[o];
#pragma unroll
        for (int t = 0; t < 3; t++) {
            int off = (h + 1 + dr[t]) * 17 + (w + 1 + dc[t]);
            acc += mw[(t * DM + o) * 2 + 0] * xp[off]
                 + mw[(t * DM + o) * 2 + 1] * xp[PADP + off];
        }
        dst[o * PSTR + p] = silu(acc);
    }
}

// -------- tensor-core directional 3-tap conv 128->128 + silu --------
// x split to bf16 hi/lo, pixel-major smem tiles [pad_pixel][channel].
// W (bf16 hi/lo, [o][i]) staged per tap. mma.m16n8k16; 3 mma per product
// (hi*hi + hi*lo + lo*hi) into f32 accumulators.
// Warp (wid) = (m_tile = wid&7 -> 16 o-channels, n_half = wid>>3 -> 15 n-tiles of 8 px).
__global__ __launch_bounds__(512, 1) void k_dirconv_mma(
    const float* __restrict__ srcb, float* __restrict__ dstb,
    const __nv_bfloat16* __restrict__ wh,   // [3][128][136]
    const __nv_bfloat16* __restrict__ wl,
    const float* __restrict__ bias) {
    extern __shared__ char smem[];
    char* xh  = smem;
    char* xl  = smem + XT_BYTES;
    char* wsh = smem + 2 * XT_BYTES;
    char* wsl = wsh + WT_BYTES;
    int b = blockIdx.x, d = blockIdx.y;
    int tid = threadIdx.x, lane = tid & 31, wid = tid >> 5;
    const float* src = srcb + (size_t)(d * NB + b) * DM * PSTR;
    float*       dst = dstb + (size_t)(d * NB + b) * DM * PSTR;

    // zero x tiles (borders must be 0)
    for (int i = tid * 16; i < 2 * XT_BYTES; i += 512 * 16)
        *(float4*)(smem + i) = make_float4(0.f, 0.f, 0.f, 0.f);
    __syncthreads();
    // fill interior: split to bf16 hi/lo, transposed [rp][c]
    for (int idx = tid; idx < DM * NPIX; idx += 512) {
        int c = idx / NPIX, p = idx - c * NPIX;
        int h = p / 15, w = p - h * 15;
        int rp = (h + 1) * 17 + (w + 1);
        float v = src[c * PSTR + p];
        __nv_bfloat16 hi = __float2bfloat16(v);
        __nv_bfloat16 lo = __float2bfloat16(v - __bfloat162float(hi));
        *(__nv_bfloat16*)(xh + rp * XROWB + c * 2) = hi;
        *(__nv_bfloat16*)(xl + rp * XROWB + c * 2) = lo;
    }

    const int g  = lane >> 2;       // 0..7
    const int t4 = lane & 3;        // 0..3
    const int mb = (wid & 7) * 16;  // o-tile base
    const int nh = wid >> 3;        // n-half

    // per-thread B row byte offsets for 15 n-tiles (p >= 225 clamped; results discarded)
    int rowb[15];
#pragma unroll
    for (int nt = 0; nt < 15; nt++) {
        int p = (nh * 15 + nt) * 8 + g;
        int pc = (p < NPIX) ? p : (NPIX - 1);
        int h = pc / 15, w = pc - h * 15;
        rowb[nt] = ((h + 1) * 17 + (w + 1)) * XROWB;
    }

    float acc[15][4];
#pragma unroll
    for (int nt = 0; nt < 15; nt++) {
        acc[nt][0] = 0.f; acc[nt][1] = 0.f; acc[nt][2] = 0.f; acc[nt][3] = 0.f;
    }

    int dlt[3];
#pragma unroll
    for (int t = 0; t < 3; t++) dlt[t] = (c_dr[d][t] * 17 + c_dc[d][t]) * XROWB;

    for (int tp = 0; tp < 3; tp++) {
        __syncthreads();   // previous tap's W readers done; (tp=0) x tiles visible
        {
            const float4* sh = (const float4*)(wh + tp * 128 * 136);
            const float4* sl = (const float4*)(wl + tp * 128 * 136);
            float4* dh = (float4*)wsh;
            float4* dl = (float4*)wsl;
            for (int i = tid; i < WT_BYTES / 16; i += 512) { dh[i] = sh[i]; dl[i] = sl[i]; }
        }
        __syncthreads();
        const int dl0 = dlt[tp];

#pragma unroll
        for (int ks = 0; ks < 8; ks++) {
            int kb = ks * 32 + t4 * 4;
            const char* ah = wsh + (mb + g) * WROWB + kb;
            uint a0h = *(const uint*)(ah);
            uint a1h = *(const uint*)(ah + 8 * WROWB);
            uint a2h = *(const uint*)(ah + 16);
            uint a3h = *(const uint*)(ah + 8 * WROWB + 16);
            const char* al = wsl + (mb + g) * WROWB + kb;
            uint a0l = *(const uint*)(al);
            uint a1l = *(const uint*)(al + 8 * WROWB);
            uint a2l = *(const uint*)(al + 16);
            uint a3l = *(const uint*)(al + 8 * WROWB + 16);
#pragma unroll
            for (int nt = 0; nt < 15; nt++) {
                const char* bp = xh + (rowb[nt] + dl0 + kb);
                uint b0h = *(const uint*)(bp);
                uint b1h = *(const uint*)(bp + 16);
                const char* bq = xl + (rowb[nt] + dl0 + kb);
                uint b0l = *(const uint*)(bq);
                uint b1l = *(const uint*)(bq + 16);
                mma_bf16(acc[nt], a0h, a1h, a2h, a3h, b0h, b1h);  // hi*hi
                mma_bf16(acc[nt], a0h, a1h, a2h, a3h, b0l, b1l);  // Whi*xlo
                mma_bf16(acc[nt], a0l, a1l, a2l, a3l, b0h, b1h);  // Wlo*xhi
            }
        }
    }

    // epilogue: C[row=g(+8)][col=2*t4(+1)] per tile; silu + bias; skip p>=225
#pragma unroll
    for (int nt = 0; nt < 15; nt++) {
        int pb = (nh * 15 + nt) * 8 + 2 * t4;
        if (pb < NPIX) {
            int o = mb + g;
            float bv = bias[o];
            dst[o * PSTR + pb] = silu(acc[nt][0] + bv);
            if (pb + 1 < NPIX) dst[o * PSTR + pb + 1] = silu(acc[nt][1] + bv);
            float bv2 = bias[o + 8];
            dst[(o + 8) * PSTR + pb] = silu(acc[nt][2] + bv2);
            if (pb + 1 < NPIX) dst[(o + 8) * PSTR + pb + 1] = silu(acc[nt][3] + bv2);
        }
    }
}

// -------- pointwise 128->128 + silu; ADD=1: dst = dst + silu(pw(src)) --------
template <int ADD>
__global__ __launch_bounds__(512, 1) void k_pw(const float* __restrict__ srcb,
                                               const float* __restrict__ wT,
                                               const float* __restrict__ bias,
                                               float* __restrict__ dstb) {
    extern __shared__ float smbuf[];
    float* xsm = smbuf;              // DM*XST
    float* wsm = smbuf + DM * XST;   // DM*DM
    int b = blockIdx.x, d = blockIdx.y;
    int tid = threadIdx.x, lane = tid & 31, wid = tid >> 5;
    const float* src = srcb + (size_t)(d * NB + b) * DM * PSTR;
    float*       dst = dstb + (size_t)(d * NB + b) * DM * PSTR;

    for (int c = wid; c < DM; c += 16) {
        const float* s = src + c * PSTR;
        float* xq = xsm + c * XST;
        for (int p = lane; p < NPIX; p += 32) xq[p] = s[p];
        if (lane < 31) xq[NPIX + lane] = 0.f;
    }
    {
        const float4* ws = (const float4*)wT;
        float4* wd = (float4*)wsm;
#pragma unroll
        for (int j = 0; j < 8; j++) wd[tid + 512 * j] = ws[tid + 512 * j];
    }
    __syncthreads();

    const int pg    = wid >> 3;
    const int obase = (wid & 7) * 16;
    const int pbase = pg * 128 + lane;

    ull acc[8][4];
#pragma unroll
    for (int j = 0; j < 8; j++)
#pragma unroll
        for (int k = 0; k < 4; k++) acc[j][k] = 0ull;

    for (int i = 0; i < DM; i++) {
        const float* wrow = wsm + i * DM + obase;
        ulonglong2 wa = *(const ulonglong2*)(wrow);
        ulonglong2 wb = *(const ulonglong2*)(wrow + 4);
        ulonglong2 wc = *(const ulonglong2*)(wrow + 8);
        ulonglong2 we = *(const ulonglong2*)(wrow + 12);
        const float* xr = xsm + i * XST + pbase;
#pragma unroll
        for (int k = 0; k < 4; k++) {
            float xv = xr[32 * k];
            ull xx = pack2(xv, xv);
            acc[0][k] = fma2(xx, wa.x, acc[0][k]);
            acc[1][k] = fma2(xx, wa.y, acc[1][k]);
            acc[2][k] = fma2(xx, wb.x, acc[2][k]);
            acc[3][k] = fma2(xx, wb.y, acc[3][k]);
            acc[4][k] = fma2(xx, wc.x, acc[4][k]);
            acc[5][k] = fma2(xx, wc.y, acc[5][k]);
            acc[6][k] = fma2(xx, we.x, acc[6][k]);
            acc[7][k] = fma2(xx, we.y, acc[7][k]);
        }
    }
#pragma unroll
    for (int j = 0; j < 8; j++) {
        int o0 = obase + 2 * j;
        float b0 = bias[o0], b1 = bias[o0 + 1];
        float* d0 = dst + o0 * PSTR;
        float* d1 = d0 + PSTR;
#pragma unroll
        for (int k = 0; k < 4; k++) {
            int p = pbase + 32 * k;
            if (p < NPIX) {
                float2 v = unpack2(acc[j][k]);
                float y0 = silu(v.x + b0), y1 = silu(v.y + b1);
                if (ADD) { y0 += d0[p]; y1 += d1[p]; }
                d0[p] = y0;
                d1[p] = y1;
            }
        }
    }
}

// -------- fused: fin(128->64) per dir, tanh-clamp, sum dirs, prelu/4, heads --------
__global__ __launch_bounds__(256, 1) void k_fin(
    const float* __restrict__ xsb, const float* __restrict__ wT,
    const float* __restrict__ bias, const float* __restrict__ prelu,
    const float* __restrict__ pdww, const float* __restrict__ pdwb,
    const float* __restrict__ ppw,
    const float* __restrict__ vl1w, const float* __restrict__ vl1b,
    const float* __restrict__ vl2w, const float* __restrict__ vl2b,
    const float* __restrict__ vlfw, const float* __restrict__ vlfb,
    const float* __restrict__ pscale, const float* __restrict__ vscale,
    float* __restrict__ out) {
    extern __shared__ float sm[];
    float* xsm  = sm;              // DM*XST
    float* facc = sm + DM * XST;   // DOUT*PADP
    __shared__ float vbuf[32], h1[32], h2[32];
    int b = blockIdx.x, tid = threadIdx.x, lane = tid & 31, wid = tid >> 5;

    for (int i = tid; i < DOUT * PADP; i += 256) facc[i] = 0.f;

    for (int d = 0; d < 4; d++) {
        __syncthreads();
        const float* src = xsb + (size_t)(d * NB + b) * DM * PSTR;
        for (int c = wid; c < DM; c += 8) {
            const float* s = src + c * PSTR;
            float* xq = xsm + c * XST;
            for (int p = lane; p < NPIX; p += 32) xq[p] = s[p];
            if (lane < 31) xq[NPIX + lane] = 0.f;
        }
        __syncthreads();

        for (int pass = 0; pass < 2; pass++) {
            int obase = pass * 32 + wid * 4;
            ull acc[4][4];
#pragma unroll
            for (int j = 0; j < 4; j++)
#pragma unroll
                for (int k = 0; k < 4; k++) acc[j][k] = 0ull;

#pragma unroll 4
            for (int i = 0; i < DM; i++) {
                float4 wv = *(const float4*)(wT + i * DOUT + obase);
                ull w0 = pack2(wv.x, wv.x), w1 = pack2(wv.y, wv.y);
                ull w2 = pack2(wv.z, wv.z), w3 = pack2(wv.w, wv.w);
                const ull* xr = (const ull*)(xsm + i * XST) + lane;
#pragma unroll
                for (int k = 0; k < 4; k++) {
                    ull xx = xr[32 * k];
                    acc[0][k] = fma2(xx, w0, acc[0][k]);
                    acc[1][k] = fma2(xx, w1, acc[1][k]);
                    acc[2][k] = fma2(xx, w2, acc[2][k]);
                    acc[3][k] = fma2(xx, w3, acc[3][k]);
                }
            }
#pragma unroll
            for (int j = 0; j < 4; j++) {
                int o = obase + j;
                float bv = bias[o];
                float* fo = facc + o * PADP;
#pragma unroll
                for (int k = 0; k < 4; k++) {
                    int px = 2 * (lane + 32 * k);
                    float2 v = unpack2(acc[j][k]);
                    if (px < NPIX) {
                        int h = px / 15, w = px - h * 15;
                        fo[(h + 1) * 17 + w + 1] += MAXF * tanhf((v.x + bv) * INV_MAXF);
                    }
                    if (px + 1 < NPIX) {
                        int h = (px + 1) / 15, w = (px + 1) - h * 15;
                        fo[(h + 1) * 17 + w + 1] += MAXF * tanhf((v.y + bv) * INV_MAXF);
                    }
                }
            }
        }
    }
    __syncthreads();

    for (int idx = tid; idx < DOUT * NPIX; idx += 256) {
        int o = idx / NPIX, p = idx - o * NPIX;
        int h = p / 15, w = p - h * 15;
        float* fp = &facc[o * PADP + (h + 1) * 17 + w + 1];
        float v = *fp;
        *fp = (v >= 0.f ? v : prelu[o] * v) * 0.25f;
    }
    __syncthreads();

    if (tid < NPIX) {
        int h = tid / 15, w = tid - h * 15;
        int base = (h + 1) * 17 + (w + 1);
        float acc = 0.f;
        for (int c = 0; c < DP; c++) {
            const float* fc = facc + c * PADP + base;
            const float* wk = pdww + c * 9;
            float s = pdwb[c];
#pragma unroll
            for (int r = 0; r < 3; r++)
#pragma unroll
                for (int cc = 0; cc < 3; cc++)
                    s += wk[r * 3 + cc] * fc[(r - 1) * 17 + (cc - 1)];
            s = (s >= 0.f) ? s : s * 0.0625f;
            s = fminf(fmaxf(s, -MAXF), MAXF);
            acc += ppw[c] * s;
        }
        acc = (acc >= 0.f) ? acc : acc * 0.0625f;
        out[NB * 3 + (size_t)b * NPIX + tid] = acc * pscale[0];
    }
    __syncthreads();

    if (wid == 0) {
        const float* fc = facc + (DP + lane) * PADP;
        float s = 0.f;
        for (int h = 0; h < 15; h++)
#pragma unroll
            for (int w = 0; w < 15; w++) s += fc[(h + 1) * 17 + w + 1];
        vbuf[lane] = fmaxf(s * (1.f / 225.f), 0.f);
        __syncwarp();
        float a = vl1b[lane];
        for (int i = 0; i < 32; i++) a += vl1w[lane * 32 + i] * vbuf[i];
        h1[lane] = fminf(fmaxf(a, 0.f), MAXM);
        __syncwarp();
        float g = vl2b[lane];
        for (int i = 0; i < 32; i++) g += vl2w[lane * 32 + i] * h1[i];
        h2[lane] = fminf(fmaxf(g, 0.f), MAXM);
        __syncwarp();
        if (lane < 3) {
            float o = vlfb[lane];
            for (int i = 0; i < 32; i++) o += vlfw[lane * 32 + i] * h2[i];
            out[(size_t)b * 3 + lane] = o * vscale[0];
        }
    }
}

// ---------------- host ----------------
extern "C" void kernel_launch(void* const* d_in, const int* in_sizes, int n_in,
                              void* d_out, int out_size) {
    const float* x       = (const float*)d_in[0];
    const float* map_w   = (const float*)d_in[1];
    const float* map_b   = (const float*)d_in[2];
    const float* dconv_w = (const float*)d_in[3];
    const float* dconv_b = (const float*)d_in[4];
    const float* c1_w    = (const float*)d_in[5];
    const float* c1_b    = (const float*)d_in[6];
    const float* r0_w1   = (const float*)d_in[7];
    const float* r0_b1   = (const float*)d_in[8];
    const float* r0_w2   = (const float*)d_in[9];
    const float* r0_b2   = (const float*)d_in[10];
    const float* fin_w   = (const float*)d_in[11];
    const float* fin_b   = (const float*)d_in[12];
    const float* prelu_w = (const float*)d_in[13];
    const float* pdw_w   = (const float*)d_in[14];
    const float* pdw_b   = (const float*)d_in[15];
    const float* ppw_w   = (const float*)d_in[16];
    const float* vl1_w   = (const float*)d_in[17];
    const float* vl1_b   = (const float*)d_in[18];
    const float* vl2_w   = (const float*)d_in[19];
    const float* vl2_b   = (const float*)d_in[20];
    const float* vlf_w   = (const float*)d_in[21];
    const float* vlf_b   = (const float*)d_in[22];
    const float* pscale  = (const float*)d_in[23];
    const float* vscale  = (const float*)d_in[24];
    float* out = (float*)d_out;

    float *xs, *tmp, *wc1, *wr1, *wr2, *wfn;
    __nv_bfloat16 *wdh, *wdl;
    cudaGetSymbolAddress((void**)&xs,  g_xs);
    cudaGetSymbolAddress((void**)&tmp, g_tmp);
    cudaGetSymbolAddress((void**)&wdh, g_wdch);
    cudaGetSymbolAddress((void**)&wdl, g_wdcl);
    cudaGetSymbolAddress((void**)&wc1, g_wc1);
    cudaGetSymbolAddress((void**)&wr1, g_wr1);
    cudaGetSymbolAddress((void**)&wr2, g_wr2);
    cudaGetSymbolAddress((void**)&wfn, g_wfn);

    cudaFuncSetAttribute(k_dirconv_mma, cudaFuncAttributeMaxDynamicSharedMemorySize, SMD);
    cudaFuncSetAttribute(k_pw<0>, cudaFuncAttributeMaxDynamicSharedMemorySize, SMB);
    cudaFuncSetAttribute(k_pw<1>, cudaFuncAttributeMaxDynamicSharedMemorySize, SMB);
    cudaFuncSetAttribute(k_fin,   cudaFuncAttributeMaxDynamicSharedMemorySize, SMC);

    // launches 1-2: weight prep (ncu -s 5 -c 1 lands on k_dirconv_mma layer 2)
    k_prep_dconv<<<256, 256>>>(dconv_w, wdh, wdl);
    k_xpose_rest<<<128, 256>>>(c1_w, r0_w1, r0_w2, fin_w, wc1, wr1, wr2, wfn);

    dim3 gbd(NB, 4);
    k_map<<<gbd, 256>>>(x, map_w, map_b, xs);
    for (int l = 0; l < 4; l++) {
        k_dirconv_mma<<<gbd, 512, SMD>>>(xs, tmp, wdh + l * 3 * 128 * 136,
                                         wdl + l * 3 * 128 * 136, dconv_b + l * DM);
        k_pw<1><<<gbd, 512, SMB>>>(tmp, wc1 + l * DM * DM, c1_b + l * DM, xs);
    }
    k_pw<0><<<gbd, 512, SMB>>>(xs, wr1, r0_b1, tmp);
    k_pw<1><<<gbd, 512, SMB>>>(tmp, wr2, r0_b2, xs);

    k_fin<<<NB, 256, SMC>>>(xs, wfn, fin_b, prelu_w, pdw_w, pdw_b, ppw_w,
                            vl1_w, vl1_b, vl2_w, vl2_b, vlf_w, vlf_b,
                            pscale, vscale, out);
}

// round 12
// speedup vs baseline: 2.1077x; 1.0797x over previous
#include <cuda_runtime.h>
#include <cuda_bf16.h>
#include <math.h>

typedef unsigned long long ull;
typedef unsigned int uint;

#define NB   512
#define DM   128
#define DOUT 64
#define DP   32
#define NPIX 225
#define PSTR 228
#define PADP 292
#define XST  256
#define MAXF 31.75f
#define INV_MAXF (1.0f/31.75f)
#define MAXM (127.0f/3.515625f)

// mma smem layout constants
#define XROWB 272                      // bytes per x^T row (136 bf16)
#define XROWS 289                      // padded 17x17 pixels (dirconv)
#define XT_BYTES (XROWS*XROWB)         // 78608
#define WROWB 272
#define WT_BYTES (128*WROWB)           // 34816
#define SMD (2*XT_BYTES + 2*WT_BYTES)  // 226848  (dirconv)

#define XP_BYTES (256*XROWB)           // 69632   (pw dense 256-px tile)
#define SMP (2*XP_BYTES + 2*WT_BYTES)  // 208896  (pw)

#define SMC (DM*XST*4 + DOUT*PADP*4)   // k_fin smem

// ---------------- device scratch ----------------
__device__ __align__(16) float g_xs [4ull*NB*DM*PSTR];
__device__ __align__(16) float g_tmp[4ull*NB*DM*PSTR];
// 18 weight matrices, bf16 hi/lo [18][128][136]:
//  0..11: dconv l*3+t   12..15: c1 l   16: r0_w1   17: r0_w2
__device__ __align__(16) __nv_bfloat16 g_wh[18*128*136];
__device__ __align__(16) __nv_bfloat16 g_wl[18*128*136];
__device__ __align__(16) float g_wfn[DM*DOUT];    // fin [i][o]

__constant__ int c_dr[4][3] = {{0,0,0},{-1,0,1},{-1,0,1},{1,0,-1}};
__constant__ int c_dc[4][3] = {{-1,0,1},{0,0,0},{-1,0,1},{-1,0,1}};

// ---------------- helpers ----------------
__device__ __forceinline__ ull pack2(float lo, float hi) {
    ull r; asm("mov.b64 %0, {%1,%2};" : "=l"(r) : "f"(lo), "f"(hi)); return r;
}
__device__ __forceinline__ float2 unpack2(ull v) {
    float2 f; asm("mov.b64 {%0,%1}, %2;" : "=f"(f.x), "=f"(f.y) : "l"(v)); return f;
}
__device__ __forceinline__ ull fma2(ull a, ull b, ull c) {
    ull d; asm("fma.rn.f32x2 %0, %1, %2, %3;" : "=l"(d) : "l"(a), "l"(b), "l"(c)); return d;
}
__device__ __forceinline__ float silu(float x) {
    return __fdividef(x, 1.f + __expf(-x));
}
__device__ __forceinline__ void mma_bf16(float* c,
    uint a0, uint a1, uint a2, uint a3, uint b0, uint b1) {
    asm("mma.sync.aligned.m16n8k16.row.col.f32.bf16.bf16.f32 "
        "{%0,%1,%2,%3}, {%4,%5,%6,%7}, {%8,%9}, {%0,%1,%2,%3};"
        : "+f"(c[0]), "+f"(c[1]), "+f"(c[2]), "+f"(c[3])
        : "r"(a0), "r"(a1), "r"(a2), "r"(a3), "r"(b0), "r"(b1));
}

// ---------------- weight prep: 18x f32 [o][128] -> bf16 hi/lo [o][136] ----------------
__global__ void k_prep(const float* __restrict__ dconv,
                       const float* __restrict__ c1,
                       const float* __restrict__ r1,
                       const float* __restrict__ r2,
                       __nv_bfloat16* __restrict__ wh,
                       __nv_bfloat16* __restrict__ wl) {
    int n = 18 * 128 * 136;
    for (int idx = blockIdx.x * blockDim.x + threadIdx.x; idx < n;
         idx += gridDim.x * blockDim.x) {
        int m = idx / (128 * 136);
        int rem = idx - m * 128 * 136;
        int o = rem / 136, i = rem - o * 136;
        float v = 0.f;
        if (i < 128) {
            if (m < 12)      v = dconv[(m * 128 + o) * 128 + i];
            else if (m < 16) v = c1[((m - 12) * 128 + o) * 128 + i];
            else if (m == 16) v = r1[o * 128 + i];
            else              v = r2[o * 128 + i];
        }
        __nv_bfloat16 hi = __float2bfloat16(v);
        wh[idx] = hi;
        wl[idx] = __float2bfloat16(v - __bfloat162float(hi));
    }
}

// ---------------- transpose fin weights: [o(64)][i(128)] -> [i][o] ----------------
__global__ void k_xpose_fin(const float* __restrict__ fin, float* __restrict__ wfn) {
    int n = DOUT * DM;
    for (int idx = blockIdx.x * blockDim.x + threadIdx.x; idx < n;
         idx += gridDim.x * blockDim.x) {
        int r = idx / DM, c = idx - r * DM;
        wfn[c * DOUT + r] = fin[idx];
    }
}

// ---------------- input map conv (2 -> 128) + silu ----------------
__global__ __launch_bounds__(256) void k_map(const float* __restrict__ x,
                                             const float* __restrict__ mw,
                                             const float* __restrict__ mb,
                                             float* __restrict__ xsb) {
    int b = blockIdx.x, d = blockIdx.y, tid = threadIdx.x;
    __shared__ float xp[2 * PADP];
    for (int i = tid; i < 2 * PADP; i += 256) xp[i] = 0.f;
    __syncthreads();
    const float* xb = x + (size_t)b * 2 * NPIX;
    for (int i = tid; i < 2 * NPIX; i += 256) {
        int c = i / NPIX, p = i - c * NPIX;
        int h = p / 15, w = p - h * 15;
        xp[c * PADP + (h + 1) * 17 + (w + 1)] = xb[i];
    }
    __syncthreads();
    int dr[3], dc[3];
#pragma unroll
    for (int t = 0; t < 3; t++) { dr[t] = c_dr[d][t]; dc[t] = c_dc[d][t]; }
    float* dst = xsb + (size_t)(d * NB + b) * DM * PSTR;
    for (int idx = tid; idx < DM * NPIX; idx += 256) {
        int o = idx / NPIX, p = idx - o * NPIX;
        int h = p / 15, w = p - h * 15;
        float acc = mb[o];
#pragma unroll
        for (int t = 0; t < 3; t++) {
            int off = (h + 1 + dr[t]) * 17 + (w + 1 + dc[t]);
            acc += mw[(t * DM + o) * 2 + 0] * xp[off]
                 + mw[(t * DM + o) * 2 + 1] * xp[PADP + off];
        }
        dst[o * PSTR + p] = silu(acc);
    }
}

// -------- tensor-core directional 3-tap conv 128->128 + silu (proven R10) --------
__global__ __launch_bounds__(512, 1) void k_dirconv_mma(
    const float* __restrict__ srcb, float* __restrict__ dstb,
    const __nv_bfloat16* __restrict__ wh,   // [3][128][136]
    const __nv_bfloat16* __restrict__ wl,
    const float* __restrict__ bias) {
    extern __shared__ char smem[];
    char* xh  = smem;
    char* xl  = smem + XT_BYTES;
    char* wsh = smem + 2 * XT_BYTES;
    char* wsl = wsh + WT_BYTES;
    int b = blockIdx.x, d = blockIdx.y;
    int tid = threadIdx.x, lane = tid & 31, wid = tid >> 5;
    const float* src = srcb + (size_t)(d * NB + b) * DM * PSTR;
    float*       dst = dstb + (size_t)(d * NB + b) * DM * PSTR;

    for (int i = tid * 16; i < 2 * XT_BYTES; i += 512 * 16)
        *(float4*)(smem + i) = make_float4(0.f, 0.f, 0.f, 0.f);
    __syncthreads();
    for (int idx = tid; idx < DM * NPIX; idx += 512) {
        int c = idx / NPIX, p = idx - c * NPIX;
        int h = p / 15, w = p - h * 15;
        int rp = (h + 1) * 17 + (w + 1);
        float v = src[c * PSTR + p];
        __nv_bfloat16 hi = __float2bfloat16(v);
        __nv_bfloat16 lo = __float2bfloat16(v - __bfloat162float(hi));
        *(__nv_bfloat16*)(xh + rp * XROWB + c * 2) = hi;
        *(__nv_bfloat16*)(xl + rp * XROWB + c * 2) = lo;
    }

    const int g  = lane >> 2;
    const int t4 = lane & 3;
    const int mb = (wid & 7) * 16;
    const int nh = wid >> 3;

    int rowb[15];
#pragma unroll
    for (int nt = 0; nt < 15; nt++) {
        int p = (nh * 15 + nt) * 8 + g;
        int pc = (p < NPIX) ? p : (NPIX - 1);
        int h = pc / 15, w = pc - h * 15;
        rowb[nt] = ((h + 1) * 17 + (w + 1)) * XROWB;
    }

    float acc[15][4];
#pragma unroll
    for (int nt = 0; nt < 15; nt++) {
        acc[nt][0] = 0.f; acc[nt][1] = 0.f; acc[nt][2] = 0.f; acc[nt][3] = 0.f;
    }

    int dlt[3];
#pragma unroll
    for (int t = 0; t < 3; t++) dlt[t] = (c_dr[d][t] * 17 + c_dc[d][t]) * XROWB;

    for (int tp = 0; tp < 3; tp++) {
        __syncthreads();
        {
            const float4* sh = (const float4*)(wh + tp * 128 * 136);
            const float4* sl = (const float4*)(wl + tp * 128 * 136);
            float4* dh = (float4*)wsh;
            float4* dl = (float4*)wsl;
            for (int i = tid; i < WT_BYTES / 16; i += 512) { dh[i] = sh[i]; dl[i] = sl[i]; }
        }
        __syncthreads();
        const int dl0 = dlt[tp];

#pragma unroll
        for (int ks = 0; ks < 8; ks++) {
            int kb = ks * 32 + t4 * 4;
            const char* ah = wsh + (mb + g) * WROWB + kb;
            uint a0h = *(const uint*)(ah);
            uint a1h = *(const uint*)(ah + 8 * WROWB);
            uint a2h = *(const uint*)(ah + 16);
            uint a3h = *(const uint*)(ah + 8 * WROWB + 16);
            const char* al = wsl + (mb + g) * WROWB + kb;
            uint a0l = *(const uint*)(al);
            uint a1l = *(const uint*)(al + 8 * WROWB);
            uint a2l = *(const uint*)(al + 16);
            uint a3l = *(const uint*)(al + 8 * WROWB + 16);
#pragma unroll
            for (int nt = 0; nt < 15; nt++) {
                const char* bp = xh + (rowb[nt] + dl0 + kb);
                uint b0h = *(const uint*)(bp);
                uint b1h = *(const uint*)(bp + 16);
                const char* bq = xl + (rowb[nt] + dl0 + kb);
                uint b0l = *(const uint*)(bq);
                uint b1l = *(const uint*)(bq + 16);
                mma_bf16(acc[nt], a0h, a1h, a2h, a3h, b0h, b1h);
                mma_bf16(acc[nt], a0h, a1h, a2h, a3h, b0l, b1l);
                mma_bf16(acc[nt], a0l, a1l, a2l, a3l, b0h, b1h);
            }
        }
    }

#pragma unroll
    for (int nt = 0; nt < 15; nt++) {
        int pb = (nh * 15 + nt) * 8 + 2 * t4;
        if (pb < NPIX) {
            int o = mb + g;
            float bv = bias[o];
            dst[o * PSTR + pb] = silu(acc[nt][0] + bv);
            if (pb + 1 < NPIX) dst[o * PSTR + pb + 1] = silu(acc[nt][1] + bv);
            float bv2 = bias[o + 8];
            dst[(o + 8) * PSTR + pb] = silu(acc[nt][2] + bv2);
            if (pb + 1 < NPIX) dst[(o + 8) * PSTR + pb + 1] = silu(acc[nt][3] + bv2);
        }
    }
}

// -------- tensor-core pointwise 128->128 + silu; ADD: dst += silu(pw(src)) --------
// Dense x^T tile [256 px][136 ch] bf16 hi/lo; W [o][i] hi/lo staged once.
// Warp = (m-tile wid&7 -> 16 o, n-half wid>>3 -> 16 n-tiles of 8 px).
template <int ADD>
__global__ __launch_bounds__(512, 1) void k_pw_mma(
    const float* __restrict__ srcb, float* __restrict__ dstb,
    const __nv_bfloat16* __restrict__ wh,   // [128][136]
    const __nv_bfloat16* __restrict__ wl,
    const float* __restrict__ bias) {
    extern __shared__ char smem[];
    char* xh  = smem;
    char* xl  = smem + XP_BYTES;
    char* wsh = smem + 2 * XP_BYTES;
    char* wsl = wsh + WT_BYTES;
    int b = blockIdx.x, d = blockIdx.y;
    int tid = threadIdx.x, lane = tid & 31, wid = tid >> 5;
    const float* src = srcb + (size_t)(d * NB + b) * DM * PSTR;
    float*       dst = dstb + (size_t)(d * NB + b) * DM * PSTR;

    // zero x tiles (pixels 225..255 must be 0)
    for (int i = tid * 16; i < 2 * XP_BYTES; i += 512 * 16)
        *(float4*)(smem + i) = make_float4(0.f, 0.f, 0.f, 0.f);
    __syncthreads();
    // fill + stage weights
    for (int idx = tid; idx < DM * NPIX; idx += 512) {
        int c = idx / NPIX, p = idx - c * NPIX;
        float v = src[c * PSTR + p];
        __nv_bfloat16 hi = __float2bfloat16(v);
        __nv_bfloat16 lo = __float2bfloat16(v - __bfloat162float(hi));
        *(__nv_bfloat16*)(xh + p * XROWB + c * 2) = hi;
        *(__nv_bfloat16*)(xl + p * XROWB + c * 2) = lo;
    }
    {
        const float4* sh = (const float4*)wh;
        const float4* sl = (const float4*)wl;
        float4* dh = (float4*)wsh;
        float4* dl = (float4*)wsl;
        for (int i = tid; i < WT_BYTES / 16; i += 512) { dh[i] = sh[i]; dl[i] = sl[i]; }
    }
    __syncthreads();

    const int g  = lane >> 2;
    const int t4 = lane & 3;
    const int mb = (wid & 7) * 16;
    const int nh = wid >> 3;
    const int pb0 = nh * 128;          // this warp's first pixel

    float acc[16][4];
#pragma unroll
    for (int nt = 0; nt < 16; nt++) {
        acc[nt][0] = 0.f; acc[nt][1] = 0.f; acc[nt][2] = 0.f; acc[nt][3] = 0.f;
    }

#pragma unroll
    for (int ks = 0; ks < 8; ks++) {
        int kb = ks * 32 + t4 * 4;
        const char* ah = wsh + (mb + g) * WROWB + kb;
        uint a0h = *(const uint*)(ah);
        uint a1h = *(const uint*)(ah + 8 * WROWB);
        uint a2h = *(const uint*)(ah + 16);
        uint a3h = *(const uint*)(ah + 8 * WROWB + 16);
        const char* al = wsl + (mb + g) * WROWB + kb;
        uint a0l = *(const uint*)(al);
        uint a1l = *(const uint*)(al + 8 * WROWB);
        uint a2l = *(const uint*)(al + 16);
        uint a3l = *(const uint*)(al + 8 * WROWB + 16);
        const char* xrh = xh + (pb0 + g) * XROWB + kb;
        const char* xrl = xl + (pb0 + g) * XROWB + kb;
#pragma unroll
        for (int nt = 0; nt < 16; nt++) {
            const char* bp = xrh + nt * 8 * XROWB;
            uint b0h = *(const uint*)(bp);
            uint b1h = *(const uint*)(bp + 16);
            const char* bq = xrl + nt * 8 * XROWB;
            uint b0l = *(const uint*)(bq);
            uint b1l = *(const uint*)(bq + 16);
            mma_bf16(acc[nt], a0h, a1h, a2h, a3h, b0h, b1h);
            mma_bf16(acc[nt], a0h, a1h, a2h, a3h, b0l, b1l);
            mma_bf16(acc[nt], a0l, a1l, a2l, a3l, b0h, b1h);
        }
    }

#pragma unroll
    for (int nt = 0; nt < 16; nt++) {
        int pb = pb0 + nt * 8 + 2 * t4;
        if (pb < NPIX) {
            int o = mb + g;
            float bv = bias[o];
            float* dp = dst + o * PSTR;
            float y0 = silu(acc[nt][0] + bv);
            if (ADD) y0 += dp[pb];
            dp[pb] = y0;
            if (pb + 1 < NPIX) {
                float y1 = silu(acc[nt][1] + bv);
                if (ADD) y1 += dp[pb + 1];
                dp[pb + 1] = y1;
            }
            float bv2 = bias[o + 8];
            float* dq = dst + (o + 8) * PSTR;
            float y2 = silu(acc[nt][2] + bv2);
            if (ADD) y2 += dq[pb];
            dq[pb] = y2;
            if (pb + 1 < NPIX) {
                float y3 = silu(acc[nt][3] + bv2);
                if (ADD) y3 += dq[pb + 1];
                dq[pb + 1] = y3;
            }
        }
    }
}

// -------- fused: fin(128->64) per dir, tanh-clamp, sum dirs, prelu/4, heads --------
__global__ __launch_bounds__(256, 1) void k_fin(
    const float* __restrict__ xsb, const float* __restrict__ wT,
    const float* __restrict__ bias, const float* __restrict__ prelu,
    const float* __restrict__ pdww, const float* __restrict__ pdwb,
    const float* __restrict__ ppw,
    const float* __restrict__ vl1w, const float* __restrict__ vl1b,
    const float* __restrict__ vl2w, const float* __restrict__ vl2b,
    const float* __restrict__ vlfw, const float* __restrict__ vlfb,
    const float* __restrict__ pscale, const float* __restrict__ vscale,
    float* __restrict__ out) {
    extern __shared__ float sm[];
    float* xsm  = sm;
    float* facc = sm + DM * XST;
    __shared__ float vbuf[32], h1[32], h2[32];
    int b = blockIdx.x, tid = threadIdx.x, lane = tid & 31, wid = tid >> 5;

    for (int i = tid; i < DOUT * PADP; i += 256) facc[i] = 0.f;

    for (int d = 0; d < 4; d++) {
        __syncthreads();
        const float* src = xsb + (size_t)(d * NB + b) * DM * PSTR;
        for (int c = wid; c < DM; c += 8) {
            const float* s = src + c * PSTR;
            float* xq = xsm + c * XST;
            for (int p = lane; p < NPIX; p += 32) xq[p] = s[p];
            if (lane < 31) xq[NPIX + lane] = 0.f;
        }
        __syncthreads();

        for (int pass = 0; pass < 2; pass++) {
            int obase = pass * 32 + wid * 4;
            ull acc[4][4];
#pragma unroll
            for (int j = 0; j < 4; j++)
#pragma unroll
                for (int k = 0; k < 4; k++) acc[j][k] = 0ull;

#pragma unroll 4
            for (int i = 0; i < DM; i++) {
                float4 wv = *(const float4*)(wT + i * DOUT + obase);
                ull w0 = pack2(wv.x, wv.x), w1 = pack2(wv.y, wv.y);
                ull w2 = pack2(wv.z, wv.z), w3 = pack2(wv.w, wv.w);
                const ull* xr = (const ull*)(xsm + i * XST) + lane;
#pragma unroll
                for (int k = 0; k < 4; k++) {
                    ull xx = xr[32 * k];
                    acc[0][k] = fma2(xx, w0, acc[0][k]);
                    acc[1][k] = fma2(xx, w1, acc[1][k]);
                    acc[2][k] = fma2(xx, w2, acc[2][k]);
                    acc[3][k] = fma2(xx, w3, acc[3][k]);
                }
            }
#pragma unroll
            for (int j = 0; j < 4; j++) {
                int o = obase + j;
                float bv = bias[o];
                float* fo = facc + o * PADP;
#pragma unroll
                for (int k = 0; k < 4; k++) {
                    int px = 2 * (lane + 32 * k);
                    float2 v = unpack2(acc[j][k]);
                    if (px < NPIX) {
                        int h = px / 15, w = px - h * 15;
                        fo[(h + 1) * 17 + w + 1] += MAXF * tanhf((v.x + bv) * INV_MAXF);
                    }
                    if (px + 1 < NPIX) {
                        int h = (px + 1) / 15, w = (px + 1) - h * 15;
                        fo[(h + 1) * 17 + w + 1] += MAXF * tanhf((v.y + bv) * INV_MAXF);
                    }
                }
            }
        }
    }
    __syncthreads();

    for (int idx = tid; idx < DOUT * NPIX; idx += 256) {
        int o = idx / NPIX, p = idx - o * NPIX;
        int h = p / 15, w = p - h * 15;
        float* fp = &facc[o * PADP + (h + 1) * 17 + w + 1];
        float v = *fp;
        *fp = (v >= 0.f ? v : prelu[o] * v) * 0.25f;
    }
    __syncthreads();

    if (tid < NPIX) {
        int h = tid / 15, w = tid - h * 15;
        int base = (h + 1) * 17 + (w + 1);
        float acc = 0.f;
        for (int c = 0; c < DP; c++) {
            const float* fc = facc + c * PADP + base;
            const float* wk = pdww + c * 9;
            float s = pdwb[c];
#pragma unroll
            for (int r = 0; r < 3; r++)
#pragma unroll
                for (int cc = 0; cc < 3; cc++)
                    s += wk[r * 3 + cc] * fc[(r - 1) * 17 + (cc - 1)];
            s = (s >= 0.f) ? s : s * 0.0625f;
            s = fminf(fmaxf(s, -MAXF), MAXF);
            acc += ppw[c] * s;
        }
        acc = (acc >= 0.f) ? acc : acc * 0.0625f;
        out[NB * 3 + (size_t)b * NPIX + tid] = acc * pscale[0];
    }
    __syncthreads();

    if (wid == 0) {
        const float* fc = facc + (DP + lane) * PADP;
        float s = 0.f;
        for (int h = 0; h < 15; h++)
#pragma unroll
            for (int w = 0; w < 15; w++) s += fc[(h + 1) * 17 + w + 1];
        vbuf[lane] = fmaxf(s * (1.f / 225.f), 0.f);
        __syncwarp();
        float a = vl1b[lane];
        for (int i = 0; i < 32; i++) a += vl1w[lane * 32 + i] * vbuf[i];
        h1[lane] = fminf(fmaxf(a, 0.f), MAXM);
        __syncwarp();
        float g = vl2b[lane];
        for (int i = 0; i < 32; i++) g += vl2w[lane * 32 + i] * h1[i];
        h2[lane] = fminf(fmaxf(g, 0.f), MAXM);
        __syncwarp();
        if (lane < 3) {
            float o = vlfb[lane];
            for (int i = 0; i < 32; i++) o += vlfw[lane * 32 + i] * h2[i];
            out[(size_t)b * 3 + lane] = o * vscale[0];
        }
    }
}

// ---------------- host ----------------
extern "C" void kernel_launch(void* const* d_in, const int* in_sizes, int n_in,
                              void* d_out, int out_size) {
    const float* x       = (const float*)d_in[0];
    const float* map_w   = (const float*)d_in[1];
    const float* map_b   = (const float*)d_in[2];
    const float* dconv_w = (const float*)d_in[3];
    const float* dconv_b = (const float*)d_in[4];
    const float* c1_w    = (const float*)d_in[5];
    const float* c1_b    = (const float*)d_in[6];
    const float* r0_w1   = (const float*)d_in[7];
    const float* r0_b1   = (const float*)d_in[8];
    const float* r0_w2   = (const float*)d_in[9];
    const float* r0_b2   = (const float*)d_in[10];
    const float* fin_w   = (const float*)d_in[11];
    const float* fin_b   = (const float*)d_in[12];
    const float* prelu_w = (const float*)d_in[13];
    const float* pdw_w   = (const float*)d_in[14];
    const float* pdw_b   = (const float*)d_in[15];
    const float* ppw_w   = (const float*)d_in[16];
    const float* vl1_w   = (const float*)d_in[17];
    const float* vl1_b   = (const float*)d_in[18];
    const float* vl2_w   = (const float*)d_in[19];
    const float* vl2_b   = (const float*)d_in[20];
    const float* vlf_w   = (const float*)d_in[21];
    const float* vlf_b   = (const float*)d_in[22];
    const float* pscale  = (const float*)d_in[23];
    const float* vscale  = (const float*)d_in[24];
    float* out = (float*)d_out;

    float *xs, *tmp, *wfn;
    __nv_bfloat16 *wh, *wl;
    cudaGetSymbolAddress((void**)&xs,  g_xs);
    cudaGetSymbolAddress((void**)&tmp, g_tmp);
    cudaGetSymbolAddress((void**)&wh,  g_wh);
    cudaGetSymbolAddress((void**)&wl,  g_wl);
    cudaGetSymbolAddress((void**)&wfn, g_wfn);

    cudaFuncSetAttribute(k_dirconv_mma, cudaFuncAttributeMaxDynamicSharedMemorySize, SMD);
    cudaFuncSetAttribute(k_pw_mma<0>, cudaFuncAttributeMaxDynamicSharedMemorySize, SMP);
    cudaFuncSetAttribute(k_pw_mma<1>, cudaFuncAttributeMaxDynamicSharedMemorySize, SMP);
    cudaFuncSetAttribute(k_fin, cudaFuncAttributeMaxDynamicSharedMemorySize, SMC);

    const int MS = 128 * 136;   // elements per prepped matrix

    // launches 1-2: weight prep
    k_prep<<<256, 256>>>(dconv_w, c1_w, r0_w1, r0_w2, wh, wl);
    k_xpose_fin<<<32, 256>>>(fin_w, wfn);

    dim3 gbd(NB, 4);
    k_map<<<gbd, 256>>>(x, map_w, map_b, xs);                       // launch 3
    for (int l = 0; l < 4; l++) {
        k_dirconv_mma<<<gbd, 512, SMD>>>(xs, tmp, wh + l * 3 * MS,  // 4,6,8,10
                                         wl + l * 3 * MS, dconv_b + l * DM);
        k_pw_mma<1><<<gbd, 512, SMP>>>(tmp, xs, wh + (12 + l) * MS, // 5,7,9,11
                                       wl + (12 + l) * MS, c1_b + l * DM);
    }
    k_pw_mma<0><<<gbd, 512, SMP>>>(xs, tmp, wh + 16 * MS, wl + 16 * MS, r0_b1);
    k_pw_mma<1><<<gbd, 512, SMP>>>(tmp, xs, wh + 17 * MS, wl + 17 * MS, r0_b2);

    k_fin<<<NB, 256, SMC>>>(xs, wfn, fin_b, prelu_w, pdw_w, pdw_b, ppw_w,
                            vl1_w, vl1_b, vl2_w, vl2_b, vlf_w, vlf_b,
                            pscale, vscale, out);
}